// round 8
// baseline (speedup 1.0000x reference)
#include <cuda_runtime.h>
#include <math.h>

// Problem constants
#define T_TOKENS 25088      // 8 * 3136
#define DMODEL   768
#define NHEAD    12
#define DHEAD    64
#define FFDIM    3072
#define WS2      49
#define NWIN     512        // T_TOKENS / 49
#define D3       2304       // 3 * DMODEL

// ---------------- scratch (device globals; no allocation allowed) ----------------
__device__ __align__(128) float g_qkv[(size_t)T_TOKENS * D3];
__device__ __align__(128) float g_h[(size_t)T_TOKENS * DMODEL];
__device__ __align__(128) float g_o[(size_t)T_TOKENS * DMODEL];
__device__ __align__(128) float g_f[(size_t)T_TOKENS * FFDIM];
// int8 hi/lo planes + row scales
__device__ __align__(128) signed char g_xh[(size_t)T_TOKENS * DMODEL];
__device__ __align__(128) signed char g_xl[(size_t)T_TOKENS * DMODEL];
__device__ __align__(128) float       g_sx[T_TOKENS];
__device__ __align__(128) signed char g_fh[(size_t)T_TOKENS * FFDIM];
__device__ __align__(128) signed char g_fl[(size_t)T_TOKENS * FFDIM];
__device__ __align__(128) float       g_sf[T_TOKENS];
__device__ __align__(128) signed char g_wh[(size_t)FFDIM * DMODEL];
__device__ __align__(128) signed char g_wl[(size_t)FFDIM * DMODEL];
__device__ __align__(128) float       g_sw[FFDIM];

// ---------------- LayerNorm + row quantization: one block per token ---------------
__global__ __launch_bounds__(256) void ln_kernel(
    const float* __restrict__ x, const float* __restrict__ w,
    const float* __restrict__ b, signed char* __restrict__ yh,
    signed char* __restrict__ yl, float* __restrict__ yscale)
{
    const int t = blockIdx.x;
    const float* xr = x + (size_t)t * DMODEL;
    const int tid = threadIdx.x;

    float v0 = xr[tid];
    float v1 = xr[tid + 256];
    float v2 = xr[tid + 512];
    float s = v0 + v1 + v2;
    float q = v0 * v0 + v1 * v1 + v2 * v2;

    #pragma unroll
    for (int off = 16; off > 0; off >>= 1) {
        s += __shfl_xor_sync(0xFFFFFFFFu, s, off);
        q += __shfl_xor_sync(0xFFFFFFFFu, q, off);
    }
    __shared__ float ss[8], sq[8];
    const int wid = tid >> 5, lid = tid & 31;
    if (lid == 0) { ss[wid] = s; sq[wid] = q; }
    __syncthreads();
    if (tid == 0) {
        float S = 0.f, Q = 0.f;
        #pragma unroll
        for (int i = 0; i < 8; i++) { S += ss[i]; Q += sq[i]; }
        float m = S * (1.0f / DMODEL);
        float var = Q * (1.0f / DMODEL) - m * m;
        ss[0] = m;
        sq[0] = rsqrtf(var + 1e-5f);
    }
    __syncthreads();
    const float m = ss[0], r = sq[0];
    float o0 = (v0 - m) * r * w[tid]       + b[tid];
    float o1 = (v1 - m) * r * w[tid + 256] + b[tid + 256];
    float o2 = (v2 - m) * r * w[tid + 512] + b[tid + 512];

    // rowmax reduce
    float mx = fmaxf(fabsf(o0), fmaxf(fabsf(o1), fabsf(o2)));
    #pragma unroll
    for (int off = 16; off > 0; off >>= 1)
        mx = fmaxf(mx, __shfl_xor_sync(0xFFFFFFFFu, mx, off));
    __syncthreads();
    if (lid == 0) ss[wid] = mx;
    __syncthreads();
    if (tid == 0) {
        float M = 1e-20f;
        #pragma unroll
        for (int i = 0; i < 8; i++) M = fmaxf(M, ss[i]);
        ss[0] = M;
    }
    __syncthreads();
    const float M = ss[0];
    const float inv = 32600.f / M;
    if (tid == 0) yscale[t] = M * (1.f / 32600.f);

    signed char* yhr = yh + (size_t)t * DMODEL;
    signed char* ylr = yl + (size_t)t * DMODEL;
    int q0 = __float2int_rn(o0 * inv);
    int q1 = __float2int_rn(o1 * inv);
    int q2 = __float2int_rn(o2 * inv);
    int h0 = (q0 + 128) >> 8;
    int h1 = (q1 + 128) >> 8;
    int h2 = (q2 + 128) >> 8;
    yhr[tid]       = (signed char)h0;
    yhr[tid + 256] = (signed char)h1;
    yhr[tid + 512] = (signed char)h2;
    ylr[tid]       = (signed char)(q0 - (h0 << 8));
    ylr[tid + 256] = (signed char)(q1 - (h1 << 8));
    ylr[tid + 512] = (signed char)(q2 - (h2 << 8));
}

// ---------------- row quantizer: one block per row, K <= 3072 ----------------
__global__ __launch_bounds__(256) void quant_kernel(
    const float* __restrict__ src, signed char* __restrict__ hi,
    signed char* __restrict__ lo, float* __restrict__ scale, int K)
{
    __shared__ float sv[FFDIM];
    __shared__ float red[8];
    const int row = blockIdx.x;
    const int tid = threadIdx.x;
    const int wid = tid >> 5, lid = tid & 31;
    const float* sr = src + (size_t)row * K;

    float mx = 0.f;
    for (int c = tid; c < K; c += 256) {
        float v = sr[c];
        sv[c] = v;
        mx = fmaxf(mx, fabsf(v));
    }
    #pragma unroll
    for (int off = 16; off > 0; off >>= 1)
        mx = fmaxf(mx, __shfl_xor_sync(0xFFFFFFFFu, mx, off));
    if (lid == 0) red[wid] = mx;
    __syncthreads();
    if (tid == 0) {
        float M = 1e-20f;
        #pragma unroll
        for (int i = 0; i < 8; i++) M = fmaxf(M, red[i]);
        red[0] = M;
    }
    __syncthreads();
    const float M = red[0];
    const float inv = 32600.f / M;
    if (tid == 0) scale[row] = M * (1.f / 32600.f);

    for (int c = tid; c < K; c += 256) {
        int q = __float2int_rn(sv[c] * inv);
        int h = (q + 128) >> 8;
        hi[(size_t)row * K + c] = (signed char)h;
        lo[(size_t)row * K + c] = (signed char)(q - (h << 8));
    }
}

// ---------------- Windowed attention: g_qkv -> fp32 o ----------------
__global__ __launch_bounds__(256) void attn_kernel(
    const float* __restrict__ qkv, float* __restrict__ o)
{
    __shared__ float sq[WS2 * DHEAD];
    __shared__ float sk[WS2 * DHEAD];
    __shared__ float sv[WS2 * DHEAD];
    __shared__ float sscr[WS2 * WS2];

    const int w  = blockIdx.x / NHEAD;
    const int hd = blockIdx.x % NHEAD;
    const int t0 = w * WS2;
    const int tid = threadIdx.x;

    for (int i = tid; i < WS2 * DHEAD; i += 256) {
        int r = i / DHEAD, d = i % DHEAD;
        size_t base = (size_t)(t0 + r) * D3 + hd * DHEAD + d;
        sq[i] = qkv[base];
        sk[i] = qkv[base + DMODEL];
        sv[i] = qkv[base + 2 * DMODEL];
    }
    __syncthreads();

    for (int i = tid; i < WS2 * WS2; i += 256) {
        int qi = i / WS2, kj = i % WS2;
        float acc = 0.f;
        #pragma unroll
        for (int d = 0; d < DHEAD; d++)
            acc = fmaf(sq[qi * DHEAD + d], sk[kj * DHEAD + d], acc);
        sscr[i] = acc * 0.125f;
    }
    __syncthreads();

    if (tid < WS2) {
        float mx = -1e30f;
        #pragma unroll 7
        for (int j = 0; j < WS2; j++) mx = fmaxf(mx, sscr[tid * WS2 + j]);
        float sum = 0.f;
        #pragma unroll 7
        for (int j = 0; j < WS2; j++) {
            float e = __expf(sscr[tid * WS2 + j] - mx);
            sscr[tid * WS2 + j] = e;
            sum += e;
        }
        float inv = 1.0f / sum;
        #pragma unroll 7
        for (int j = 0; j < WS2; j++) sscr[tid * WS2 + j] *= inv;
    }
    __syncthreads();

    for (int i = tid; i < WS2 * DHEAD; i += 256) {
        int qi = i / DHEAD, d = i % DHEAD;
        float acc = 0.f;
        #pragma unroll
        for (int kj = 0; kj < WS2; kj++)
            acc = fmaf(sscr[qi * WS2 + kj], sv[kj * DHEAD + d], acc);
        o[(size_t)(t0 + qi) * DMODEL + hd * DHEAD + d] = acc;
    }
}

// ---------------- asm helpers ----------------
__device__ __forceinline__ unsigned smem_u32(const void* p)
{
    unsigned a;
    asm volatile("{ .reg .u64 t; cvta.to.shared.u64 t, %1; cvt.u32.u64 %0, t; }"
                 : "=r"(a) : "l"(p));
    return a;
}

__device__ __forceinline__ void ldsm4a(int* r, unsigned addr)
{
    asm volatile("ldmatrix.sync.aligned.m8n8.x4.shared.b16 {%0,%1,%2,%3}, [%4];"
                 : "=r"(r[0]), "=r"(r[1]), "=r"(r[2]), "=r"(r[3]) : "r"(addr));
}

__device__ __forceinline__ void mma_i8(int* c, const int* a, int b0, int b1)
{
    asm volatile("mma.sync.aligned.m16n8k32.row.col.s32.s8.s8.s32 "
                 "{%0,%1,%2,%3}, {%4,%5,%6,%7}, {%8,%9}, {%0,%1,%2,%3};"
                 : "+r"(c[0]), "+r"(c[1]), "+r"(c[2]), "+r"(c[3])
                 : "r"(a[0]), "r"(a[1]), "r"(a[2]), "r"(a[3]), "r"(b0), "r"(b1));
}

__device__ __forceinline__ void cp16(unsigned dst, const void* src)
{
    asm volatile("cp.async.cg.shared.global [%0], [%1], 16;"
                 :: "r"(dst), "l"(src) : "memory");
}

__device__ __forceinline__ void cp_commit()
{
    asm volatile("cp.async.commit_group;" ::: "memory");
}

__device__ __forceinline__ void cp_wait1()
{
    asm volatile("cp.async.wait_group 1;" ::: "memory");
}

__device__ __forceinline__ void cp_wait0()
{
    asm volatile("cp.async.wait_group 0;" ::: "memory");
}

// ---------------- int8 split tensor-core GEMM ----------------
// C[M,N] = act(A @ B^T + bias) (+ res), A = sa*(256*Ah+Al), B = sb*(256*Bh+Bl).
// C = sa*sb*(65536*hh + 256*cross) (AlBl dropped, ~5e-5 rel).
// Block 128x128, K-chunk 64, 8 warps (warp 64x32), mma.m16n8k32.s8, cp.async x2 stages.
#define ROWB 80                      // smem bytes per row (64 data + 16 pad)
#define PLANEB (128 * ROWB)          // 10240
#define STAGEB (4 * PLANEB)          // 40960
#define SMEMB  (2 * STAGEB)          // 81920

template <bool GELU, bool RES>
__global__ __launch_bounds__(256) void gemm_i8(
    const signed char* __restrict__ Ah, const signed char* __restrict__ Al,
    const float* __restrict__ sa,
    const signed char* __restrict__ Bh, const signed char* __restrict__ Bl,
    const float* __restrict__ sb,
    const float* __restrict__ bias,
    const float* __restrict__ res,
    float* __restrict__ C,
    int N, int K)
{
    extern __shared__ unsigned char dsm[];
    const unsigned sbase = smem_u32(dsm);
    const int tid = threadIdx.x;
    const int lane = tid & 31;
    const int wid = tid >> 5;
    const int wm = wid & 1;
    const int wn = wid >> 1;
    const int bm = blockIdx.y * 128;
    const int bn = blockIdx.x * 128;

    int hh[4][4][4];
    int cr[4][4][4];
    #pragma unroll
    for (int i = 0; i < 4; i++)
        #pragma unroll
        for (int j = 0; j < 4; j++)
            #pragma unroll
            for (int k = 0; k < 4; k++) { hh[i][j][k] = 0; cr[i][j][k] = 0; }

    // loader: rows r0 and r0+64, 16B chunk ch of the 64B k-chunk row
    const int r0 = tid >> 2;
    const int ch = tid & 3;
    const signed char* gAh = Ah + (size_t)(bm + r0) * K + ch * 16;
    const signed char* gAl = Al + (size_t)(bm + r0) * K + ch * 16;
    const signed char* gBh = Bh + (size_t)(bn + r0) * K + ch * 16;
    const signed char* gBl = Bl + (size_t)(bn + r0) * K + ch * 16;
    const size_t rstep = (size_t)64 * K;
    const unsigned drow0 = r0 * ROWB + ch * 16;
    const unsigned drow1 = (r0 + 64) * ROWB + ch * 16;
    const int nkc = K / 64;

    // prologue: stage 0, chunk 0
    {
        const unsigned st = sbase;
        cp16(st + drow0,              gAh);
        cp16(st + drow1,              gAh + rstep);
        cp16(st + PLANEB + drow0,     gAl);
        cp16(st + PLANEB + drow1,     gAl + rstep);
        cp16(st + 2 * PLANEB + drow0, gBh);
        cp16(st + 2 * PLANEB + drow1, gBh + rstep);
        cp16(st + 3 * PLANEB + drow0, gBl);
        cp16(st + 3 * PLANEB + drow1, gBl + rstep);
        cp_commit();
    }

    for (int kc = 0; kc < nkc; kc++) {
        if (kc + 1 < nkc) {
            const unsigned st = sbase + ((kc + 1) & 1) * STAGEB;
            const int ko = (kc + 1) * 64;
            cp16(st + drow0,              gAh + ko);
            cp16(st + drow1,              gAh + ko + rstep);
            cp16(st + PLANEB + drow0,     gAl + ko);
            cp16(st + PLANEB + drow1,     gAl + ko + rstep);
            cp16(st + 2 * PLANEB + drow0, gBh + ko);
            cp16(st + 2 * PLANEB + drow1, gBh + ko + rstep);
            cp16(st + 3 * PLANEB + drow0, gBl + ko);
            cp16(st + 3 * PLANEB + drow1, gBl + ko + rstep);
            cp_commit();
            cp_wait1();
        } else {
            cp_wait0();
        }
        __syncthreads();

        const unsigned st = sbase + (kc & 1) * STAGEB;
        #pragma unroll
        for (int ks = 0; ks < 2; ks++) {
            const unsigned abase = st + (wm * 64 + (lane & 15)) * ROWB
                                   + ks * 32 + ((lane >> 4) << 4);
            const unsigned bbase = st + 2 * PLANEB + (wn * 32 + (lane & 15)) * ROWB
                                   + ks * 32 + ((lane >> 4) << 4);
            int ah[4][4], al[4][4];
            #pragma unroll
            for (int mi = 0; mi < 4; mi++) {
                ldsm4a(ah[mi], abase + mi * 16 * ROWB);
                ldsm4a(al[mi], abase + PLANEB + mi * 16 * ROWB);
            }
            int bh[2][4], bl[2][4];
            #pragma unroll
            for (int nj = 0; nj < 2; nj++) {
                ldsm4a(bh[nj], bbase + nj * 16 * ROWB);
                ldsm4a(bl[nj], bbase + PLANEB + nj * 16 * ROWB);
            }
            #pragma unroll
            for (int mi = 0; mi < 4; mi++) {
                #pragma unroll
                for (int ni = 0; ni < 4; ni++) {
                    const int nj = ni >> 1;
                    const int sel = ni & 1;
                    mma_i8(hh[mi][ni], ah[mi], bh[nj][sel], bh[nj][sel + 2]);
                    mma_i8(cr[mi][ni], ah[mi], bl[nj][sel], bl[nj][sel + 2]);
                    mma_i8(cr[mi][ni], al[mi], bh[nj][sel], bh[nj][sel + 2]);
                }
            }
        }
        __syncthreads();
    }

    // epilogue
    #pragma unroll
    for (int mi = 0; mi < 4; mi++) {
        #pragma unroll
        for (int ni = 0; ni < 4; ni++) {
            const int col = bn + wn * 32 + ni * 8 + (lane & 3) * 2;
            const float sb0 = sb[col];
            const float sb1 = sb[col + 1];
            const float bs0 = bias[col];
            const float bs1 = bias[col + 1];
            #pragma unroll
            for (int half = 0; half < 2; half++) {
                const int row = bm + wm * 64 + mi * 16 + (lane >> 2) + half * 8;
                const float sra = sa[row];
                float v0 = sra * sb0 * (65536.f * (float)hh[mi][ni][half * 2 + 0]
                                        + 256.f * (float)cr[mi][ni][half * 2 + 0]) + bs0;
                float v1 = sra * sb1 * (65536.f * (float)hh[mi][ni][half * 2 + 1]
                                        + 256.f * (float)cr[mi][ni][half * 2 + 1]) + bs1;
                if (GELU) {
                    v0 = 0.5f * v0 * (1.0f + erff(v0 * 0.70710678118654752f));
                    v1 = 0.5f * v1 * (1.0f + erff(v1 * 0.70710678118654752f));
                }
                if (RES) {
                    float2 r2 = *(const float2*)(res + (size_t)row * N + col);
                    v0 += r2.x;
                    v1 += r2.y;
                }
                float2 o2;
                o2.x = v0;
                o2.y = v1;
                *(float2*)(C + (size_t)row * N + col) = o2;
            }
        }
    }
}

// ---------------- host-side launch ----------------
extern "C" void kernel_launch(void* const* d_in, const int* in_sizes, int n_in,
                              void* d_out, int out_size)
{
    const float* x     = (const float*)d_in[0];
    const float* Wqkv  = (const float*)d_in[1];
    const float* bqkv  = (const float*)d_in[2];
    const float* Wo    = (const float*)d_in[3];
    const float* bo    = (const float*)d_in[4];
    const float* ln1_w = (const float*)d_in[5];
    const float* ln1_b = (const float*)d_in[6];
    const float* W1    = (const float*)d_in[7];
    const float* b1    = (const float*)d_in[8];
    const float* W2    = (const float*)d_in[9];
    const float* b2    = (const float*)d_in[10];
    const float* ln2_w = (const float*)d_in[11];
    const float* ln2_b = (const float*)d_in[12];
    float* out = (float*)d_out;

    static float *p_qkv = nullptr, *p_h = nullptr, *p_o = nullptr, *p_f = nullptr;
    static float *p_sx = nullptr, *p_sf = nullptr, *p_sw = nullptr;
    static signed char *p_xh = nullptr, *p_xl = nullptr;
    static signed char *p_fh = nullptr, *p_fl = nullptr;
    static signed char *p_wh = nullptr, *p_wl = nullptr;
    if (!p_qkv) {
        cudaGetSymbolAddress((void**)&p_qkv, g_qkv);
        cudaGetSymbolAddress((void**)&p_h,   g_h);
        cudaGetSymbolAddress((void**)&p_o,   g_o);
        cudaGetSymbolAddress((void**)&p_f,   g_f);
        cudaGetSymbolAddress((void**)&p_sx,  g_sx);
        cudaGetSymbolAddress((void**)&p_sf,  g_sf);
        cudaGetSymbolAddress((void**)&p_sw,  g_sw);
        cudaGetSymbolAddress((void**)&p_xh,  g_xh);
        cudaGetSymbolAddress((void**)&p_xl,  g_xl);
        cudaGetSymbolAddress((void**)&p_fh,  g_fh);
        cudaGetSymbolAddress((void**)&p_fl,  g_fl);
        cudaGetSymbolAddress((void**)&p_wh,  g_wh);
        cudaGetSymbolAddress((void**)&p_wl,  g_wl);
        cudaFuncSetAttribute(gemm_i8<false, false>,
                             cudaFuncAttributeMaxDynamicSharedMemorySize, SMEMB);
        cudaFuncSetAttribute(gemm_i8<false, true>,
                             cudaFuncAttributeMaxDynamicSharedMemorySize, SMEMB);
        cudaFuncSetAttribute(gemm_i8<true, false>,
                             cudaFuncAttributeMaxDynamicSharedMemorySize, SMEMB);
    }

    const dim3 blk(256);
    const dim3 grid_qkv(D3 / 128,    T_TOKENS / 128);
    const dim3 grid_d  (DMODEL / 128, T_TOKENS / 128);
    const dim3 grid_ff (FFDIM / 128,  T_TOKENS / 128);

    for (int l = 0; l < 2; l++) {
        const float* hin  = (l == 0) ? x : p_h;
        float* hout2 = (l == 1) ? out : p_h;

        // pre-norm attention
        ln_kernel<<<T_TOKENS, blk>>>(hin, ln1_w + l * DMODEL, ln1_b + l * DMODEL,
                                     p_xh, p_xl, p_sx);
        quant_kernel<<<D3, blk>>>(Wqkv + (size_t)l * D3 * DMODEL, p_wh, p_wl, p_sw, DMODEL);
        gemm_i8<false, false><<<grid_qkv, blk, SMEMB>>>(
            p_xh, p_xl, p_sx, p_wh, p_wl, p_sw,
            bqkv + (size_t)l * D3, nullptr, p_qkv, D3, DMODEL);
        attn_kernel<<<NWIN * NHEAD, blk>>>(p_qkv, p_o);
        quant_kernel<<<T_TOKENS, blk>>>(p_o, p_xh, p_xl, p_sx, DMODEL);
        quant_kernel<<<DMODEL, blk>>>(Wo + (size_t)l * DMODEL * DMODEL, p_wh, p_wl, p_sw, DMODEL);
        gemm_i8<false, true><<<grid_d, blk, SMEMB>>>(
            p_xh, p_xl, p_sx, p_wh, p_wl, p_sw,
            bo + (size_t)l * DMODEL, hin, p_h, DMODEL, DMODEL);

        // pre-norm FFN
        ln_kernel<<<T_TOKENS, blk>>>(p_h, ln2_w + l * DMODEL, ln2_b + l * DMODEL,
                                     p_xh, p_xl, p_sx);
        quant_kernel<<<FFDIM, blk>>>(W1 + (size_t)l * FFDIM * DMODEL, p_wh, p_wl, p_sw, DMODEL);
        gemm_i8<true, false><<<grid_ff, blk, SMEMB>>>(
            p_xh, p_xl, p_sx, p_wh, p_wl, p_sw,
            b1 + (size_t)l * FFDIM, nullptr, p_f, FFDIM, DMODEL);
        quant_kernel<<<T_TOKENS, blk>>>(p_f, p_fh, p_fl, p_sf, FFDIM);
        quant_kernel<<<DMODEL, blk>>>(W2 + (size_t)l * DMODEL * FFDIM, p_wh, p_wl, p_sw, FFDIM);
        gemm_i8<false, true><<<grid_d, blk, SMEMB>>>(
            p_fh, p_fl, p_sf, p_wh, p_wl, p_sw,
            b2 + (size_t)l * DMODEL, p_h, hout2, DMODEL, FFDIM);
    }
    (void)in_sizes; (void)n_in; (void)out_size;
}

// round 9
// speedup vs baseline: 2.8586x; 2.8586x over previous
#include <cuda_runtime.h>
#include <math.h>

// Problem constants
#define T_TOKENS 25088      // 8 * 3136
#define DMODEL   768
#define NHEAD    12
#define DHEAD    64
#define FFDIM    3072
#define WS2      49
#define NWIN     512        // T_TOKENS / 49
#define D3       2304       // 3 * DMODEL

// ---------------- scratch (device globals; no allocation allowed) ----------------
__device__ __align__(128) float g_qkv[(size_t)T_TOKENS * D3];
__device__ __align__(128) float g_h[(size_t)T_TOKENS * DMODEL];
// bf16 hi/lo planes
__device__ __align__(128) unsigned short g_yh[(size_t)T_TOKENS * DMODEL];
__device__ __align__(128) unsigned short g_yl[(size_t)T_TOKENS * DMODEL];
__device__ __align__(128) unsigned short g_oh[(size_t)T_TOKENS * DMODEL];
__device__ __align__(128) unsigned short g_ol[(size_t)T_TOKENS * DMODEL];
__device__ __align__(128) unsigned short g_fh[(size_t)T_TOKENS * FFDIM];
__device__ __align__(128) unsigned short g_fl[(size_t)T_TOKENS * FFDIM];
__device__ __align__(128) unsigned short g_wh[(size_t)FFDIM * DMODEL];
__device__ __align__(128) unsigned short g_wl[(size_t)FFDIM * DMODEL];

// ---------------- bf16 helpers (pure bit ops) ----------------
__device__ __forceinline__ unsigned f2bf(float f)
{
    unsigned u = __float_as_uint(f);
    return (u + 0x7FFFu + ((u >> 16) & 1u)) >> 16;
}

__device__ __forceinline__ float bf2f(unsigned h)
{
    return __uint_as_float(h << 16);
}

// ---------------- weight split: fp32 -> hi/lo bf16 planes ----------------
__global__ __launch_bounds__(256) void split_kernel(
    const float* __restrict__ src, unsigned short* __restrict__ hi,
    unsigned short* __restrict__ lo)
{
    const int i = (blockIdx.x * 256 + threadIdx.x) * 4;
    float4 v = *(const float4*)(src + i);
    unsigned h0 = f2bf(v.x);
    unsigned h1 = f2bf(v.y);
    unsigned h2 = f2bf(v.z);
    unsigned h3 = f2bf(v.w);
    unsigned l0 = f2bf(v.x - bf2f(h0));
    unsigned l1 = f2bf(v.y - bf2f(h1));
    unsigned l2 = f2bf(v.z - bf2f(h2));
    unsigned l3 = f2bf(v.w - bf2f(h3));
    uint2 ph;
    ph.x = h0 | (h1 << 16);
    ph.y = h2 | (h3 << 16);
    *(uint2*)(hi + i) = ph;
    uint2 pl;
    pl.x = l0 | (l1 << 16);
    pl.y = l2 | (l3 << 16);
    *(uint2*)(lo + i) = pl;
}

// ---------------- LayerNorm: one block per token; writes hi/lo planes -------------
__global__ __launch_bounds__(256) void ln_kernel(
    const float* __restrict__ x, const float* __restrict__ w,
    const float* __restrict__ b, unsigned short* __restrict__ yh,
    unsigned short* __restrict__ yl)
{
    const int t = blockIdx.x;
    const float* xr = x + (size_t)t * DMODEL;
    unsigned short* yhr = yh + (size_t)t * DMODEL;
    unsigned short* ylr = yl + (size_t)t * DMODEL;
    const int tid = threadIdx.x;

    float v0 = xr[tid];
    float v1 = xr[tid + 256];
    float v2 = xr[tid + 512];
    float s = v0 + v1 + v2;
    float q = v0 * v0 + v1 * v1 + v2 * v2;

    #pragma unroll
    for (int off = 16; off > 0; off >>= 1) {
        s += __shfl_xor_sync(0xFFFFFFFFu, s, off);
        q += __shfl_xor_sync(0xFFFFFFFFu, q, off);
    }
    __shared__ float ss[8], sq[8];
    const int wid = tid >> 5, lid = tid & 31;
    if (lid == 0) { ss[wid] = s; sq[wid] = q; }
    __syncthreads();
    if (tid == 0) {
        float S = 0.f, Q = 0.f;
        #pragma unroll
        for (int i = 0; i < 8; i++) { S += ss[i]; Q += sq[i]; }
        float m = S * (1.0f / DMODEL);
        float var = Q * (1.0f / DMODEL) - m * m;
        ss[0] = m;
        sq[0] = rsqrtf(var + 1e-5f);
    }
    __syncthreads();
    const float m = ss[0], r = sq[0];
    float o0 = (v0 - m) * r * w[tid]       + b[tid];
    float o1 = (v1 - m) * r * w[tid + 256] + b[tid + 256];
    float o2 = (v2 - m) * r * w[tid + 512] + b[tid + 512];
    unsigned h0 = f2bf(o0);
    unsigned h1 = f2bf(o1);
    unsigned h2 = f2bf(o2);
    yhr[tid]       = (unsigned short)h0;
    yhr[tid + 256] = (unsigned short)h1;
    yhr[tid + 512] = (unsigned short)h2;
    ylr[tid]       = (unsigned short)f2bf(o0 - bf2f(h0));
    ylr[tid + 256] = (unsigned short)f2bf(o1 - bf2f(h1));
    ylr[tid + 512] = (unsigned short)f2bf(o2 - bf2f(h2));
}

// ---------------- Windowed attention (register-tiled): g_qkv -> o hi/lo planes ----
// Padded to 56 rows; q/k/v row stride 68 floats; scores 56x56 (stride 56).
// Phase1: 196 threads, 4x4 tile over 56x56, K=64. Phase2: 208 threads, 4x4 over 52x64.
#define AP 56
#define QSTR 68
#define ATTN_SMEM ((3 * AP * QSTR + AP * AP) * 4)   // 58240 bytes

__global__ __launch_bounds__(256) void attn_kernel(
    const float* __restrict__ qkv, unsigned short* __restrict__ oh,
    unsigned short* __restrict__ ol)
{
    extern __shared__ float asmem[];
    float* sq = asmem;
    float* sk = sq + AP * QSTR;
    float* sv = sk + AP * QSTR;
    float* sp = sv + AP * QSTR;

    const int w  = blockIdx.x / NHEAD;
    const int hd = blockIdx.x % NHEAD;
    const int t0 = w * WS2;
    const int tid = threadIdx.x;

    for (int i = tid; i < AP * DHEAD; i += 256) {
        int r = i >> 6;
        int d = i & 63;
        float q = 0.f, k = 0.f, v = 0.f;
        if (r < WS2) {
            size_t base = (size_t)(t0 + r) * D3 + hd * DHEAD + d;
            q = qkv[base];
            k = qkv[base + DMODEL];
            v = qkv[base + 2 * DMODEL];
        }
        sq[r * QSTR + d] = q;
        sk[r * QSTR + d] = k;
        sv[r * QSTR + d] = v;
    }
    __syncthreads();

    // phase 1: scores (4x4 per thread)
    {
        const int tj = tid % 14;
        const int ti = tid / 14;
        if (ti < 14) {
            float acc[4][4];
            #pragma unroll
            for (int i = 0; i < 4; i++)
                #pragma unroll
                for (int j = 0; j < 4; j++) acc[i][j] = 0.f;
            for (int d = 0; d < DHEAD; d++) {
                float ra[4], rb[4];
                #pragma unroll
                for (int i = 0; i < 4; i++) ra[i] = sq[(ti * 4 + i) * QSTR + d];
                #pragma unroll
                for (int j = 0; j < 4; j++) rb[j] = sk[(tj * 4 + j) * QSTR + d];
                #pragma unroll
                for (int i = 0; i < 4; i++)
                    #pragma unroll
                    for (int j = 0; j < 4; j++)
                        acc[i][j] = fmaf(ra[i], rb[j], acc[i][j]);
            }
            #pragma unroll
            for (int i = 0; i < 4; i++)
                #pragma unroll
                for (int j = 0; j < 4; j++)
                    sp[(ti * 4 + i) * AP + tj * 4 + j] = acc[i][j] * 0.125f;
        }
    }
    __syncthreads();

    // softmax per row (rows < 49, cols < 49)
    if (tid < WS2) {
        float mx = -1e30f;
        #pragma unroll 7
        for (int j = 0; j < WS2; j++) mx = fmaxf(mx, sp[tid * AP + j]);
        float sum = 0.f;
        #pragma unroll 7
        for (int j = 0; j < WS2; j++) {
            float e = __expf(sp[tid * AP + j] - mx);
            sp[tid * AP + j] = e;
            sum += e;
        }
        float inv = 1.0f / sum;
        #pragma unroll 7
        for (int j = 0; j < WS2; j++) sp[tid * AP + j] *= inv;
    }
    __syncthreads();

    // phase 2: out = P @ V (4x4 per thread)
    {
        const int tj = tid % 16;      // d block
        const int ti = tid / 16;      // row block
        if (ti < 13) {
            float acc[4][4];
            #pragma unroll
            for (int i = 0; i < 4; i++)
                #pragma unroll
                for (int j = 0; j < 4; j++) acc[i][j] = 0.f;
            for (int kj = 0; kj < WS2; kj++) {
                float ra[4], rb[4];
                #pragma unroll
                for (int i = 0; i < 4; i++) ra[i] = sp[(ti * 4 + i) * AP + kj];
                #pragma unroll
                for (int j = 0; j < 4; j++) rb[j] = sv[kj * QSTR + tj * 4 + j];
                #pragma unroll
                for (int i = 0; i < 4; i++)
                    #pragma unroll
                    for (int j = 0; j < 4; j++)
                        acc[i][j] = fmaf(ra[i], rb[j], acc[i][j]);
            }
            #pragma unroll
            for (int i = 0; i < 4; i++) {
                const int qi = ti * 4 + i;
                if (qi < WS2) {
                    size_t obase = (size_t)(t0 + qi) * DMODEL + hd * DHEAD + tj * 4;
                    #pragma unroll
                    for (int j = 0; j < 4; j++) {
                        unsigned h = f2bf(acc[i][j]);
                        oh[obase + j] = (unsigned short)h;
                        ol[obase + j] = (unsigned short)f2bf(acc[i][j] - bf2f(h));
                    }
                }
            }
        }
    }
}

// ---------------- asm helpers ----------------
__device__ __forceinline__ unsigned smem_u32(const void* p)
{
    unsigned a;
    asm volatile("{ .reg .u64 t; cvta.to.shared.u64 t, %1; cvt.u32.u64 %0, t; }"
                 : "=r"(a) : "l"(p));
    return a;
}

__device__ __forceinline__ void ldsm4a(unsigned* r, unsigned addr)
{
    asm volatile("ldmatrix.sync.aligned.m8n8.x4.shared.b16 {%0,%1,%2,%3}, [%4];"
                 : "=r"(r[0]), "=r"(r[1]), "=r"(r[2]), "=r"(r[3]) : "r"(addr));
}

__device__ __forceinline__ void mma16816(float* c, const unsigned* a, unsigned b0, unsigned b1)
{
    asm volatile("mma.sync.aligned.m16n8k16.row.col.f32.bf16.bf16.f32 "
                 "{%0,%1,%2,%3}, {%4,%5,%6,%7}, {%8,%9}, {%0,%1,%2,%3};"
                 : "+f"(c[0]), "+f"(c[1]), "+f"(c[2]), "+f"(c[3])
                 : "r"(a[0]), "r"(a[1]), "r"(a[2]), "r"(a[3]), "r"(b0), "r"(b1));
}

__device__ __forceinline__ void cp16(unsigned dst, const void* src)
{
    asm volatile("cp.async.cg.shared.global [%0], [%1], 16;"
                 :: "r"(dst), "l"(src) : "memory");
}

__device__ __forceinline__ void cp_commit()
{
    asm volatile("cp.async.commit_group;" ::: "memory");
}

__device__ __forceinline__ void cp_wait1()
{
    asm volatile("cp.async.wait_group 1;" ::: "memory");
}

__device__ __forceinline__ void cp_wait0()
{
    asm volatile("cp.async.wait_group 0;" ::: "memory");
}

// ---------------- bf16x3 tensor-core GEMM (cp.async 2-stage pipeline) --------------
// C = act(A @ B^T + bias) (+ res); planes [M,K]/[N,K]; block 128x128, K-chunk 32 bf16.
// 8 warps, warp tile 64x32, mma.m16n8k16; smem rows 80B (64B data + 16B pad).
#define ROWB 80
#define PLANEB (128 * ROWB)          // 10240
#define STAGEB (4 * PLANEB)          // 40960
#define SMEMB  (2 * STAGEB)          // 81920

template <bool GELU, bool RES, bool SPLITOUT>
__global__ __launch_bounds__(256) void gemm_tc(
    const unsigned short* __restrict__ Ah, const unsigned short* __restrict__ Al,
    const unsigned short* __restrict__ Bh, const unsigned short* __restrict__ Bl,
    const float* __restrict__ bias,
    const float* __restrict__ res,
    float* __restrict__ C,
    unsigned short* __restrict__ Ch, unsigned short* __restrict__ Cl,
    int N, int K)
{
    extern __shared__ unsigned char dsm[];
    const unsigned sbase = smem_u32(dsm);
    const int tid = threadIdx.x;
    const int lane = tid & 31;
    const int wid = tid >> 5;
    const int wm = wid & 1;
    const int wn = wid >> 1;
    const int bm = blockIdx.y * 128;
    const int bn = blockIdx.x * 128;

    float acc[4][4][4];
    #pragma unroll
    for (int i = 0; i < 4; i++)
        #pragma unroll
        for (int j = 0; j < 4; j++)
            #pragma unroll
            for (int k = 0; k < 4; k++) acc[i][j][k] = 0.f;

    // loader: rows r0 and r0+64, 16B chunk ch (8 bf16) of the 64B k-chunk row
    const int r0 = tid >> 2;
    const int ch = tid & 3;
    const unsigned short* gAh = Ah + (size_t)(bm + r0) * K + ch * 8;
    const unsigned short* gAl = Al + (size_t)(bm + r0) * K + ch * 8;
    const unsigned short* gBh = Bh + (size_t)(bn + r0) * K + ch * 8;
    const unsigned short* gBl = Bl + (size_t)(bn + r0) * K + ch * 8;
    const size_t rstep = (size_t)64 * K;
    const unsigned drow0 = r0 * ROWB + ch * 16;
    const unsigned drow1 = (r0 + 64) * ROWB + ch * 16;
    const int nkc = K / 32;

    // prologue: stage 0, chunk 0
    {
        const unsigned st = sbase;
        cp16(st + drow0,              gAh);
        cp16(st + drow1,              gAh + rstep);
        cp16(st + PLANEB + drow0,     gAl);
        cp16(st + PLANEB + drow1,     gAl + rstep);
        cp16(st + 2 * PLANEB + drow0, gBh);
        cp16(st + 2 * PLANEB + drow1, gBh + rstep);
        cp16(st + 3 * PLANEB + drow0, gBl);
        cp16(st + 3 * PLANEB + drow1, gBl + rstep);
        cp_commit();
    }

    for (int kc = 0; kc < nkc; kc++) {
        if (kc + 1 < nkc) {
            const unsigned st = sbase + ((kc + 1) & 1) * STAGEB;
            const int ko = (kc + 1) * 32;
            cp16(st + drow0,              gAh + ko);
            cp16(st + drow1,              gAh + ko + rstep);
            cp16(st + PLANEB + drow0,     gAl + ko);
            cp16(st + PLANEB + drow1,     gAl + ko + rstep);
            cp16(st + 2 * PLANEB + drow0, gBh + ko);
            cp16(st + 2 * PLANEB + drow1, gBh + ko + rstep);
            cp16(st + 3 * PLANEB + drow0, gBl + ko);
            cp16(st + 3 * PLANEB + drow1, gBl + ko + rstep);
            cp_commit();
            cp_wait1();
        } else {
            cp_wait0();
        }
        __syncthreads();

        const unsigned st = sbase + (kc & 1) * STAGEB;
        #pragma unroll
        for (int ks = 0; ks < 2; ks++) {
            const unsigned abase = st + (wm * 64 + (lane & 15)) * ROWB
                                   + ks * 32 + ((lane >> 4) << 4);
            const unsigned bbase = st + 2 * PLANEB + (wn * 32 + (lane & 15)) * ROWB
                                   + ks * 32 + ((lane >> 4) << 4);
            unsigned ah[4][4], al[4][4];
            #pragma unroll
            for (int mi = 0; mi < 4; mi++) {
                ldsm4a(ah[mi], abase + mi * 16 * ROWB);
                ldsm4a(al[mi], abase + PLANEB + mi * 16 * ROWB);
            }
            unsigned bh[2][4], bl[2][4];
            #pragma unroll
            for (int nj = 0; nj < 2; nj++) {
                ldsm4a(bh[nj], bbase + nj * 16 * ROWB);
                ldsm4a(bl[nj], bbase + PLANEB + nj * 16 * ROWB);
            }
            #pragma unroll
            for (int mi = 0; mi < 4; mi++) {
                #pragma unroll
                for (int ni = 0; ni < 4; ni++) {
                    const int nj = ni >> 1;
                    const int sel = ni & 1;
                    mma16816(acc[mi][ni], ah[mi], bh[nj][sel], bh[nj][sel + 2]); // Ah*Bh
                    mma16816(acc[mi][ni], ah[mi], bl[nj][sel], bl[nj][sel + 2]); // Ah*Bl
                    mma16816(acc[mi][ni], al[mi], bh[nj][sel], bh[nj][sel + 2]); // Al*Bh
                }
            }
        }
        __syncthreads();
    }

    // epilogue
    #pragma unroll
    for (int mi = 0; mi < 4; mi++) {
        #pragma unroll
        for (int ni = 0; ni < 4; ni++) {
            const int col = bn + wn * 32 + ni * 8 + (lane & 3) * 2;
            const float bs0 = bias[col];
            const float bs1 = bias[col + 1];
            #pragma unroll
            for (int half = 0; half < 2; half++) {
                const int row = bm + wm * 64 + mi * 16 + (lane >> 2) + half * 8;
                float v0 = acc[mi][ni][half * 2 + 0] + bs0;
                float v1 = acc[mi][ni][half * 2 + 1] + bs1;
                if (GELU) {
                    v0 = 0.5f * v0 * (1.0f + erff(v0 * 0.70710678118654752f));
                    v1 = 0.5f * v1 * (1.0f + erff(v1 * 0.70710678118654752f));
                }
                if (RES) {
                    float2 r2 = *(const float2*)(res + (size_t)row * N + col);
                    v0 += r2.x;
                    v1 += r2.y;
                }
                if (SPLITOUT) {
                    unsigned h0 = f2bf(v0);
                    unsigned h1 = f2bf(v1);
                    unsigned l0 = f2bf(v0 - bf2f(h0));
                    unsigned l1 = f2bf(v1 - bf2f(h1));
                    *(unsigned*)(Ch + (size_t)row * N + col) = h0 | (h1 << 16);
                    *(unsigned*)(Cl + (size_t)row * N + col) = l0 | (l1 << 16);
                } else {
                    float2 o2;
                    o2.x = v0;
                    o2.y = v1;
                    *(float2*)(C + (size_t)row * N + col) = o2;
                }
            }
        }
    }
}

// ---------------- host-side launch ----------------
extern "C" void kernel_launch(void* const* d_in, const int* in_sizes, int n_in,
                              void* d_out, int out_size)
{
    const float* x     = (const float*)d_in[0];
    const float* Wqkv  = (const float*)d_in[1];
    const float* bqkv  = (const float*)d_in[2];
    const float* Wo    = (const float*)d_in[3];
    const float* bo    = (const float*)d_in[4];
    const float* ln1_w = (const float*)d_in[5];
    const float* ln1_b = (const float*)d_in[6];
    const float* W1    = (const float*)d_in[7];
    const float* b1    = (const float*)d_in[8];
    const float* W2    = (const float*)d_in[9];
    const float* b2    = (const float*)d_in[10];
    const float* ln2_w = (const float*)d_in[11];
    const float* ln2_b = (const float*)d_in[12];
    float* out = (float*)d_out;

    static float *p_qkv = nullptr, *p_h = nullptr;
    static unsigned short *p_yh = nullptr, *p_yl = nullptr, *p_oh = nullptr, *p_ol = nullptr;
    static unsigned short *p_fh = nullptr, *p_fl = nullptr, *p_wh = nullptr, *p_wl = nullptr;
    if (!p_qkv) {
        cudaGetSymbolAddress((void**)&p_qkv, g_qkv);
        cudaGetSymbolAddress((void**)&p_h,   g_h);
        cudaGetSymbolAddress((void**)&p_yh,  g_yh);
        cudaGetSymbolAddress((void**)&p_yl,  g_yl);
        cudaGetSymbolAddress((void**)&p_oh,  g_oh);
        cudaGetSymbolAddress((void**)&p_ol,  g_ol);
        cudaGetSymbolAddress((void**)&p_fh,  g_fh);
        cudaGetSymbolAddress((void**)&p_fl,  g_fl);
        cudaGetSymbolAddress((void**)&p_wh,  g_wh);
        cudaGetSymbolAddress((void**)&p_wl,  g_wl);
        cudaFuncSetAttribute(gemm_tc<false, false, false>,
                             cudaFuncAttributeMaxDynamicSharedMemorySize, SMEMB);
        cudaFuncSetAttribute(gemm_tc<false, true, false>,
                             cudaFuncAttributeMaxDynamicSharedMemorySize, SMEMB);
        cudaFuncSetAttribute(gemm_tc<true, false, true>,
                             cudaFuncAttributeMaxDynamicSharedMemorySize, SMEMB);
        cudaFuncSetAttribute(attn_kernel,
                             cudaFuncAttributeMaxDynamicSharedMemorySize, ATTN_SMEM);
    }

    const dim3 blk(256);
    const dim3 grid_qkv(D3 / 128,     T_TOKENS / 128);
    const dim3 grid_d  (DMODEL / 128, T_TOKENS / 128);
    const dim3 grid_ff (FFDIM / 128,  T_TOKENS / 128);

    for (int l = 0; l < 2; l++) {
        const float* hin  = (l == 0) ? x : p_h;
        float* hout2 = (l == 1) ? out : p_h;   // last FFN GEMM writes final output

        // pre-norm attention
        ln_kernel<<<T_TOKENS, blk>>>(hin, ln1_w + l * DMODEL, ln1_b + l * DMODEL, p_yh, p_yl);
        split_kernel<<<(D3 * DMODEL) / 1024, blk>>>(Wqkv + (size_t)l * D3 * DMODEL, p_wh, p_wl);
        gemm_tc<false, false, false><<<grid_qkv, blk, SMEMB>>>(
            p_yh, p_yl, p_wh, p_wl, bqkv + (size_t)l * D3,
            nullptr, p_qkv, nullptr, nullptr, D3, DMODEL);
        attn_kernel<<<NWIN * NHEAD, blk, ATTN_SMEM>>>(p_qkv, p_oh, p_ol);
        split_kernel<<<(DMODEL * DMODEL) / 1024, blk>>>(Wo + (size_t)l * DMODEL * DMODEL, p_wh, p_wl);
        gemm_tc<false, true, false><<<grid_d, blk, SMEMB>>>(
            p_oh, p_ol, p_wh, p_wl, bo + (size_t)l * DMODEL,
            hin, p_h, nullptr, nullptr, DMODEL, DMODEL);

        // pre-norm FFN
        ln_kernel<<<T_TOKENS, blk>>>(p_h, ln2_w + l * DMODEL, ln2_b + l * DMODEL, p_yh, p_yl);
        split_kernel<<<(FFDIM * DMODEL) / 1024, blk>>>(W1 + (size_t)l * FFDIM * DMODEL, p_wh, p_wl);
        gemm_tc<true, false, true><<<grid_ff, blk, SMEMB>>>(
            p_yh, p_yl, p_wh, p_wl, b1 + (size_t)l * FFDIM,
            nullptr, nullptr, p_fh, p_fl, FFDIM, DMODEL);
        split_kernel<<<(DMODEL * FFDIM) / 1024, blk>>>(W2 + (size_t)l * DMODEL * FFDIM, p_wh, p_wl);
        gemm_tc<false, true, false><<<grid_d, blk, SMEMB>>>(
            p_fh, p_fl, p_wh, p_wl, b2 + (size_t)l * DMODEL,
            p_h, hout2, nullptr, nullptr, DMODEL, FFDIM);
    }
    (void)in_sizes; (void)n_in; (void)out_size;
}

// round 10
// speedup vs baseline: 2.9745x; 1.0406x over previous
#include <cuda_runtime.h>
#include <math.h>

// Problem constants
#define T_TOKENS 25088      // 8 * 3136
#define DMODEL   768
#define NHEAD    12
#define DHEAD    64
#define FFDIM    3072
#define WS2      49
#define NWIN     512        // T_TOKENS / 49
#define D3       2304       // 3 * DMODEL

// ---------------- scratch (device globals; no allocation allowed) ----------------
__device__ __align__(128) float g_qkv[(size_t)T_TOKENS * D3];
__device__ __align__(128) float g_h[(size_t)T_TOKENS * DMODEL];
// bf16 hi/lo planes
__device__ __align__(128) unsigned short g_yh[(size_t)T_TOKENS * DMODEL];
__device__ __align__(128) unsigned short g_yl[(size_t)T_TOKENS * DMODEL];
__device__ __align__(128) unsigned short g_oh[(size_t)T_TOKENS * DMODEL];
__device__ __align__(128) unsigned short g_ol[(size_t)T_TOKENS * DMODEL];
__device__ __align__(128) unsigned short g_fh[(size_t)T_TOKENS * FFDIM];
__device__ __align__(128) unsigned short g_fl[(size_t)T_TOKENS * FFDIM];
__device__ __align__(128) unsigned short g_wh[(size_t)FFDIM * DMODEL];
__device__ __align__(128) unsigned short g_wl[(size_t)FFDIM * DMODEL];

// ---------------- bf16 helpers (pure bit ops) ----------------
__device__ __forceinline__ unsigned f2bf(float f)
{
    unsigned u = __float_as_uint(f);
    return (u + 0x7FFFu + ((u >> 16) & 1u)) >> 16;
}

__device__ __forceinline__ float bf2f(unsigned h)
{
    return __uint_as_float(h << 16);
}

// ---------------- weight split: fp32 -> hi/lo bf16 planes ----------------
__global__ __launch_bounds__(256) void split_kernel(
    const float* __restrict__ src, unsigned short* __restrict__ hi,
    unsigned short* __restrict__ lo)
{
    const int i = (blockIdx.x * 256 + threadIdx.x) * 4;
    float4 v = *(const float4*)(src + i);
    unsigned h0 = f2bf(v.x);
    unsigned h1 = f2bf(v.y);
    unsigned h2 = f2bf(v.z);
    unsigned h3 = f2bf(v.w);
    unsigned l0 = f2bf(v.x - bf2f(h0));
    unsigned l1 = f2bf(v.y - bf2f(h1));
    unsigned l2 = f2bf(v.z - bf2f(h2));
    unsigned l3 = f2bf(v.w - bf2f(h3));
    uint2 ph;
    ph.x = h0 | (h1 << 16);
    ph.y = h2 | (h3 << 16);
    *(uint2*)(hi + i) = ph;
    uint2 pl;
    pl.x = l0 | (l1 << 16);
    pl.y = l2 | (l3 << 16);
    *(uint2*)(lo + i) = pl;
}

// ---------------- LayerNorm: one block per token; writes hi/lo planes -------------
__global__ __launch_bounds__(256) void ln_kernel(
    const float* __restrict__ x, const float* __restrict__ w,
    const float* __restrict__ b, unsigned short* __restrict__ yh,
    unsigned short* __restrict__ yl)
{
    const int t = blockIdx.x;
    const float* xr = x + (size_t)t * DMODEL;
    unsigned short* yhr = yh + (size_t)t * DMODEL;
    unsigned short* ylr = yl + (size_t)t * DMODEL;
    const int tid = threadIdx.x;

    float v0 = xr[tid];
    float v1 = xr[tid + 256];
    float v2 = xr[tid + 512];
    float s = v0 + v1 + v2;
    float q = v0 * v0 + v1 * v1 + v2 * v2;

    #pragma unroll
    for (int off = 16; off > 0; off >>= 1) {
        s += __shfl_xor_sync(0xFFFFFFFFu, s, off);
        q += __shfl_xor_sync(0xFFFFFFFFu, q, off);
    }
    __shared__ float ss[8], sq[8];
    const int wid = tid >> 5, lid = tid & 31;
    if (lid == 0) { ss[wid] = s; sq[wid] = q; }
    __syncthreads();
    if (tid == 0) {
        float S = 0.f, Q = 0.f;
        #pragma unroll
        for (int i = 0; i < 8; i++) { S += ss[i]; Q += sq[i]; }
        float m = S * (1.0f / DMODEL);
        float var = Q * (1.0f / DMODEL) - m * m;
        ss[0] = m;
        sq[0] = rsqrtf(var + 1e-5f);
    }
    __syncthreads();
    const float m = ss[0], r = sq[0];
    float o0 = (v0 - m) * r * w[tid]       + b[tid];
    float o1 = (v1 - m) * r * w[tid + 256] + b[tid + 256];
    float o2 = (v2 - m) * r * w[tid + 512] + b[tid + 512];
    unsigned h0 = f2bf(o0);
    unsigned h1 = f2bf(o1);
    unsigned h2 = f2bf(o2);
    yhr[tid]       = (unsigned short)h0;
    yhr[tid + 256] = (unsigned short)h1;
    yhr[tid + 512] = (unsigned short)h2;
    ylr[tid]       = (unsigned short)f2bf(o0 - bf2f(h0));
    ylr[tid + 256] = (unsigned short)f2bf(o1 - bf2f(h1));
    ylr[tid + 512] = (unsigned short)f2bf(o2 - bf2f(h2));
}

// ---------------- Windowed attention (vectorized register-tiled) -------------------
// Padded to 56 rows; q/k/v row stride 68 floats (rows 16B-aligned); scores 56x56.
// Phase1: 196 threads, 4x4 tile over 56x56, K=64, float4 LDS.
// Phase2: 208 threads, 4x4 over 52x64, float4 V loads.
#define AP 56
#define QSTR 68
#define ATTN_SMEM ((3 * AP * QSTR + AP * AP) * 4)   // 58240 bytes

__global__ __launch_bounds__(256) void attn_kernel(
    const float* __restrict__ qkv, unsigned short* __restrict__ oh,
    unsigned short* __restrict__ ol)
{
    extern __shared__ float asmem[];
    float* sq = asmem;
    float* sk = sq + AP * QSTR;
    float* sv = sk + AP * QSTR;
    float* sp = sv + AP * QSTR;

    const int w  = blockIdx.x / NHEAD;
    const int hd = blockIdx.x % NHEAD;
    const int t0 = w * WS2;
    const int tid = threadIdx.x;

    // load q/k/v as float4 (56 rows x 16 float4)
    for (int i = tid; i < AP * 16; i += 256) {
        int r = i >> 4;
        int c4 = (i & 15) * 4;
        float4 q = make_float4(0.f, 0.f, 0.f, 0.f);
        float4 k = q;
        float4 v = q;
        if (r < WS2) {
            size_t base = (size_t)(t0 + r) * D3 + hd * DHEAD + c4;
            q = *(const float4*)(qkv + base);
            k = *(const float4*)(qkv + base + DMODEL);
            v = *(const float4*)(qkv + base + 2 * DMODEL);
        }
        *(float4*)(sq + r * QSTR + c4) = q;
        *(float4*)(sk + r * QSTR + c4) = k;
        *(float4*)(sv + r * QSTR + c4) = v;
    }
    __syncthreads();

    // phase 1: scores (4x4 per thread, float4 over d)
    {
        const int tj = tid % 14;
        const int ti = tid / 14;
        if (ti < 14) {
            float acc[4][4];
            #pragma unroll
            for (int i = 0; i < 4; i++)
                #pragma unroll
                for (int j = 0; j < 4; j++) acc[i][j] = 0.f;
            #pragma unroll 4
            for (int d = 0; d < DHEAD; d += 4) {
                float4 ra[4], rb[4];
                #pragma unroll
                for (int i = 0; i < 4; i++)
                    ra[i] = *(const float4*)(sq + (ti * 4 + i) * QSTR + d);
                #pragma unroll
                for (int j = 0; j < 4; j++)
                    rb[j] = *(const float4*)(sk + (tj * 4 + j) * QSTR + d);
                #pragma unroll
                for (int i = 0; i < 4; i++)
                    #pragma unroll
                    for (int j = 0; j < 4; j++) {
                        acc[i][j] = fmaf(ra[i].x, rb[j].x, acc[i][j]);
                        acc[i][j] = fmaf(ra[i].y, rb[j].y, acc[i][j]);
                        acc[i][j] = fmaf(ra[i].z, rb[j].z, acc[i][j]);
                        acc[i][j] = fmaf(ra[i].w, rb[j].w, acc[i][j]);
                    }
            }
            #pragma unroll
            for (int i = 0; i < 4; i++)
                #pragma unroll
                for (int j = 0; j < 4; j++)
                    sp[(ti * 4 + i) * AP + tj * 4 + j] = acc[i][j] * 0.125f;
        }
    }
    __syncthreads();

    // softmax per row (rows < 49, cols < 49)
    if (tid < WS2) {
        float mx = -1e30f;
        #pragma unroll 7
        for (int j = 0; j < WS2; j++) mx = fmaxf(mx, sp[tid * AP + j]);
        float sum = 0.f;
        #pragma unroll 7
        for (int j = 0; j < WS2; j++) {
            float e = __expf(sp[tid * AP + j] - mx);
            sp[tid * AP + j] = e;
            sum += e;
        }
        float inv = 1.0f / sum;
        #pragma unroll 7
        for (int j = 0; j < WS2; j++) sp[tid * AP + j] *= inv;
    }
    __syncthreads();

    // phase 2: out = P @ V (4x4 per thread, float4 V loads)
    {
        const int tj = tid % 16;      // d block
        const int ti = tid / 16;      // row block
        if (ti < 13) {
            float acc[4][4];
            #pragma unroll
            for (int i = 0; i < 4; i++)
                #pragma unroll
                for (int j = 0; j < 4; j++) acc[i][j] = 0.f;
            #pragma unroll 7
            for (int kj = 0; kj < WS2; kj++) {
                float4 rb = *(const float4*)(sv + kj * QSTR + tj * 4);
                float ra[4];
                #pragma unroll
                for (int i = 0; i < 4; i++) ra[i] = sp[(ti * 4 + i) * AP + kj];
                #pragma unroll
                for (int i = 0; i < 4; i++) {
                    acc[i][0] = fmaf(ra[i], rb.x, acc[i][0]);
                    acc[i][1] = fmaf(ra[i], rb.y, acc[i][1]);
                    acc[i][2] = fmaf(ra[i], rb.z, acc[i][2]);
                    acc[i][3] = fmaf(ra[i], rb.w, acc[i][3]);
                }
            }
            #pragma unroll
            for (int i = 0; i < 4; i++) {
                const int qi = ti * 4 + i;
                if (qi < WS2) {
                    size_t obase = (size_t)(t0 + qi) * DMODEL + hd * DHEAD + tj * 4;
                    unsigned h0 = f2bf(acc[i][0]);
                    unsigned h1 = f2bf(acc[i][1]);
                    unsigned h2 = f2bf(acc[i][2]);
                    unsigned h3 = f2bf(acc[i][3]);
                    unsigned l0 = f2bf(acc[i][0] - bf2f(h0));
                    unsigned l1 = f2bf(acc[i][1] - bf2f(h1));
                    unsigned l2 = f2bf(acc[i][2] - bf2f(h2));
                    unsigned l3 = f2bf(acc[i][3] - bf2f(h3));
                    *(unsigned*)(oh + obase)     = h0 | (h1 << 16);
                    *(unsigned*)(oh + obase + 2) = h2 | (h3 << 16);
                    *(unsigned*)(ol + obase)     = l0 | (l1 << 16);
                    *(unsigned*)(ol + obase + 2) = l2 | (l3 << 16);
                }
            }
        }
    }
}

// ---------------- asm helpers ----------------
__device__ __forceinline__ unsigned smem_u32(const void* p)
{
    unsigned a;
    asm volatile("{ .reg .u64 t; cvta.to.shared.u64 t, %1; cvt.u32.u64 %0, t; }"
                 : "=r"(a) : "l"(p));
    return a;
}

__device__ __forceinline__ void ldsm4a(unsigned* r, unsigned addr)
{
    asm volatile("ldmatrix.sync.aligned.m8n8.x4.shared.b16 {%0,%1,%2,%3}, [%4];"
                 : "=r"(r[0]), "=r"(r[1]), "=r"(r[2]), "=r"(r[3]) : "r"(addr));
}

__device__ __forceinline__ void mma16816(float* c, const unsigned* a, unsigned b0, unsigned b1)
{
    asm volatile("mma.sync.aligned.m16n8k16.row.col.f32.bf16.bf16.f32 "
                 "{%0,%1,%2,%3}, {%4,%5,%6,%7}, {%8,%9}, {%0,%1,%2,%3};"
                 : "+f"(c[0]), "+f"(c[1]), "+f"(c[2]), "+f"(c[3])
                 : "r"(a[0]), "r"(a[1]), "r"(a[2]), "r"(a[3]), "r"(b0), "r"(b1));
}

__device__ __forceinline__ void cp16(unsigned dst, const void* src)
{
    asm volatile("cp.async.cg.shared.global [%0], [%1], 16;"
                 :: "r"(dst), "l"(src) : "memory");
}

__device__ __forceinline__ void cp_commit()
{
    asm volatile("cp.async.commit_group;" ::: "memory");
}

__device__ __forceinline__ void cp_wait1()
{
    asm volatile("cp.async.wait_group 1;" ::: "memory");
}

__device__ __forceinline__ void cp_wait0()
{
    asm volatile("cp.async.wait_group 0;" ::: "memory");
}

// ---------------- bf16x3 tensor-core GEMM (cp.async 2-stage pipeline) --------------
// C = act(A @ B^T + bias) (+ res); planes [M,K]/[N,K]; block 128x128, K-chunk 32 bf16.
// 8 warps, warp tile 64x32, mma.m16n8k16; smem rows 80B (64B data + 16B pad).
#define ROWB 80
#define PLANEB (128 * ROWB)          // 10240
#define STAGEB (4 * PLANEB)          // 40960
#define SMEMB  (2 * STAGEB)          // 81920

template <bool GELU, bool RES, bool SPLITOUT>
__global__ __launch_bounds__(256) void gemm_tc(
    const unsigned short* __restrict__ Ah, const unsigned short* __restrict__ Al,
    const unsigned short* __restrict__ Bh, const unsigned short* __restrict__ Bl,
    const float* __restrict__ bias,
    const float* __restrict__ res,
    float* __restrict__ C,
    unsigned short* __restrict__ Ch, unsigned short* __restrict__ Cl,
    int N, int K)
{
    extern __shared__ unsigned char dsm[];
    const unsigned sbase = smem_u32(dsm);
    const int tid = threadIdx.x;
    const int lane = tid & 31;
    const int wid = tid >> 5;
    const int wm = wid & 1;
    const int wn = wid >> 1;
    const int bm = blockIdx.y * 128;
    const int bn = blockIdx.x * 128;

    float acc[4][4][4];
    #pragma unroll
    for (int i = 0; i < 4; i++)
        #pragma unroll
        for (int j = 0; j < 4; j++)
            #pragma unroll
            for (int k = 0; k < 4; k++) acc[i][j][k] = 0.f;

    // loader: rows r0 and r0+64, 16B chunk ch (8 bf16) of the 64B k-chunk row
    const int r0 = tid >> 2;
    const int ch = tid & 3;
    const unsigned short* gAh = Ah + (size_t)(bm + r0) * K + ch * 8;
    const unsigned short* gAl = Al + (size_t)(bm + r0) * K + ch * 8;
    const unsigned short* gBh = Bh + (size_t)(bn + r0) * K + ch * 8;
    const unsigned short* gBl = Bl + (size_t)(bn + r0) * K + ch * 8;
    const size_t rstep = (size_t)64 * K;
    const unsigned drow0 = r0 * ROWB + ch * 16;
    const unsigned drow1 = (r0 + 64) * ROWB + ch * 16;
    const int nkc = K / 32;

    // prologue: stage 0, chunk 0
    {
        const unsigned st = sbase;
        cp16(st + drow0,              gAh);
        cp16(st + drow1,              gAh + rstep);
        cp16(st + PLANEB + drow0,     gAl);
        cp16(st + PLANEB + drow1,     gAl + rstep);
        cp16(st + 2 * PLANEB + drow0, gBh);
        cp16(st + 2 * PLANEB + drow1, gBh + rstep);
        cp16(st + 3 * PLANEB + drow0, gBl);
        cp16(st + 3 * PLANEB + drow1, gBl + rstep);
        cp_commit();
    }

    for (int kc = 0; kc < nkc; kc++) {
        if (kc + 1 < nkc) {
            const unsigned st = sbase + ((kc + 1) & 1) * STAGEB;
            const int ko = (kc + 1) * 32;
            cp16(st + drow0,              gAh + ko);
            cp16(st + drow1,              gAh + ko + rstep);
            cp16(st + PLANEB + drow0,     gAl + ko);
            cp16(st + PLANEB + drow1,     gAl + ko + rstep);
            cp16(st + 2 * PLANEB + drow0, gBh + ko);
            cp16(st + 2 * PLANEB + drow1, gBh + ko + rstep);
            cp16(st + 3 * PLANEB + drow0, gBl + ko);
            cp16(st + 3 * PLANEB + drow1, gBl + ko + rstep);
            cp_commit();
            cp_wait1();
        } else {
            cp_wait0();
        }
        __syncthreads();

        const unsigned st = sbase + (kc & 1) * STAGEB;
        #pragma unroll
        for (int ks = 0; ks < 2; ks++) {
            const unsigned abase = st + (wm * 64 + (lane & 15)) * ROWB
                                   + ks * 32 + ((lane >> 4) << 4);
            const unsigned bbase = st + 2 * PLANEB + (wn * 32 + (lane & 15)) * ROWB
                                   + ks * 32 + ((lane >> 4) << 4);
            unsigned ah[4][4], al[4][4];
            #pragma unroll
            for (int mi = 0; mi < 4; mi++) {
                ldsm4a(ah[mi], abase + mi * 16 * ROWB);
                ldsm4a(al[mi], abase + PLANEB + mi * 16 * ROWB);
            }
            unsigned bh[2][4], bl[2][4];
            #pragma unroll
            for (int nj = 0; nj < 2; nj++) {
                ldsm4a(bh[nj], bbase + nj * 16 * ROWB);
                ldsm4a(bl[nj], bbase + PLANEB + nj * 16 * ROWB);
            }
            #pragma unroll
            for (int mi = 0; mi < 4; mi++) {
                #pragma unroll
                for (int ni = 0; ni < 4; ni++) {
                    const int nj = ni >> 1;
                    const int sel = ni & 1;
                    mma16816(acc[mi][ni], ah[mi], bh[nj][sel], bh[nj][sel + 2]); // Ah*Bh
                    mma16816(acc[mi][ni], ah[mi], bl[nj][sel], bl[nj][sel + 2]); // Ah*Bl
                    mma16816(acc[mi][ni], al[mi], bh[nj][sel], bh[nj][sel + 2]); // Al*Bh
                }
            }
        }
        __syncthreads();
    }

    // epilogue
    #pragma unroll
    for (int mi = 0; mi < 4; mi++) {
        #pragma unroll
        for (int ni = 0; ni < 4; ni++) {
            const int col = bn + wn * 32 + ni * 8 + (lane & 3) * 2;
            const float bs0 = bias[col];
            const float bs1 = bias[col + 1];
            #pragma unroll
            for (int half = 0; half < 2; half++) {
                const int row = bm + wm * 64 + mi * 16 + (lane >> 2) + half * 8;
                float v0 = acc[mi][ni][half * 2 + 0] + bs0;
                float v1 = acc[mi][ni][half * 2 + 1] + bs1;
                if (GELU) {
                    v0 = 0.5f * v0 * (1.0f + erff(v0 * 0.70710678118654752f));
                    v1 = 0.5f * v1 * (1.0f + erff(v1 * 0.70710678118654752f));
                }
                if (RES) {
                    float2 r2 = *(const float2*)(res + (size_t)row * N + col);
                    v0 += r2.x;
                    v1 += r2.y;
                }
                if (SPLITOUT) {
                    unsigned h0 = f2bf(v0);
                    unsigned h1 = f2bf(v1);
                    unsigned l0 = f2bf(v0 - bf2f(h0));
                    unsigned l1 = f2bf(v1 - bf2f(h1));
                    *(unsigned*)(Ch + (size_t)row * N + col) = h0 | (h1 << 16);
                    *(unsigned*)(Cl + (size_t)row * N + col) = l0 | (l1 << 16);
                } else {
                    float2 o2;
                    o2.x = v0;
                    o2.y = v1;
                    *(float2*)(C + (size_t)row * N + col) = o2;
                }
            }
        }
    }
}

// ---------------- host-side launch ----------------
extern "C" void kernel_launch(void* const* d_in, const int* in_sizes, int n_in,
                              void* d_out, int out_size)
{
    const float* x     = (const float*)d_in[0];
    const float* Wqkv  = (const float*)d_in[1];
    const float* bqkv  = (const float*)d_in[2];
    const float* Wo    = (const float*)d_in[3];
    const float* bo    = (const float*)d_in[4];
    const float* ln1_w = (const float*)d_in[5];
    const float* ln1_b = (const float*)d_in[6];
    const float* W1    = (const float*)d_in[7];
    const float* b1    = (const float*)d_in[8];
    const float* W2    = (const float*)d_in[9];
    const float* b2    = (const float*)d_in[10];
    const float* ln2_w = (const float*)d_in[11];
    const float* ln2_b = (const float*)d_in[12];
    float* out = (float*)d_out;

    static float *p_qkv = nullptr, *p_h = nullptr;
    static unsigned short *p_yh = nullptr, *p_yl = nullptr, *p_oh = nullptr, *p_ol = nullptr;
    static unsigned short *p_fh = nullptr, *p_fl = nullptr, *p_wh = nullptr, *p_wl = nullptr;
    if (!p_qkv) {
        cudaGetSymbolAddress((void**)&p_qkv, g_qkv);
        cudaGetSymbolAddress((void**)&p_h,   g_h);
        cudaGetSymbolAddress((void**)&p_yh,  g_yh);
        cudaGetSymbolAddress((void**)&p_yl,  g_yl);
        cudaGetSymbolAddress((void**)&p_oh,  g_oh);
        cudaGetSymbolAddress((void**)&p_ol,  g_ol);
        cudaGetSymbolAddress((void**)&p_fh,  g_fh);
        cudaGetSymbolAddress((void**)&p_fl,  g_fl);
        cudaGetSymbolAddress((void**)&p_wh,  g_wh);
        cudaGetSymbolAddress((void**)&p_wl,  g_wl);
        cudaFuncSetAttribute(gemm_tc<false, false, false>,
                             cudaFuncAttributeMaxDynamicSharedMemorySize, SMEMB);
        cudaFuncSetAttribute(gemm_tc<false, true, false>,
                             cudaFuncAttributeMaxDynamicSharedMemorySize, SMEMB);
        cudaFuncSetAttribute(gemm_tc<true, false, true>,
                             cudaFuncAttributeMaxDynamicSharedMemorySize, SMEMB);
        cudaFuncSetAttribute(attn_kernel,
                             cudaFuncAttributeMaxDynamicSharedMemorySize, ATTN_SMEM);
    }

    const dim3 blk(256);
    const dim3 grid_qkv(D3 / 128,     T_TOKENS / 128);
    const dim3 grid_d  (DMODEL / 128, T_TOKENS / 128);
    const dim3 grid_ff (FFDIM / 128,  T_TOKENS / 128);

    for (int l = 0; l < 2; l++) {
        const float* hin  = (l == 0) ? x : p_h;
        float* hout2 = (l == 1) ? out : p_h;   // last FFN GEMM writes final output

        // pre-norm attention
        ln_kernel<<<T_TOKENS, blk>>>(hin, ln1_w + l * DMODEL, ln1_b + l * DMODEL, p_yh, p_yl);
        split_kernel<<<(D3 * DMODEL) / 1024, blk>>>(Wqkv + (size_t)l * D3 * DMODEL, p_wh, p_wl);
        gemm_tc<false, false, false><<<grid_qkv, blk, SMEMB>>>(
            p_yh, p_yl, p_wh, p_wl, bqkv + (size_t)l * D3,
            nullptr, p_qkv, nullptr, nullptr, D3, DMODEL);
        attn_kernel<<<NWIN * NHEAD, blk, ATTN_SMEM>>>(p_qkv, p_oh, p_ol);
        split_kernel<<<(DMODEL * DMODEL) / 1024, blk>>>(Wo + (size_t)l * DMODEL * DMODEL, p_wh, p_wl);
        gemm_tc<false, true, false><<<grid_d, blk, SMEMB>>>(
            p_oh, p_ol, p_wh, p_wl, bo + (size_t)l * DMODEL,
            hin, p_h, nullptr, nullptr, DMODEL, DMODEL);

        // pre-norm FFN
        ln_kernel<<<T_TOKENS, blk>>>(p_h, ln2_w + l * DMODEL, ln2_b + l * DMODEL, p_yh, p_yl);
        split_kernel<<<(FFDIM * DMODEL) / 1024, blk>>>(W1 + (size_t)l * FFDIM * DMODEL, p_wh, p_wl);
        gemm_tc<true, false, true><<<grid_ff, blk, SMEMB>>>(
            p_yh, p_yl, p_wh, p_wl, b1 + (size_t)l * FFDIM,
            nullptr, nullptr, p_fh, p_fl, FFDIM, DMODEL);
        split_kernel<<<(DMODEL * FFDIM) / 1024, blk>>>(W2 + (size_t)l * DMODEL * FFDIM, p_wh, p_wl);
        gemm_tc<false, true, false><<<grid_d, blk, SMEMB>>>(
            p_fh, p_fl, p_wh, p_wl, b2 + (size_t)l * DMODEL,
            p_h, hout2, nullptr, nullptr, DMODEL, FFDIM);
    }
    (void)in_sizes; (void)n_in; (void)out_size;
}

// round 11
// speedup vs baseline: 2.9903x; 1.0053x over previous
#include <cuda_runtime.h>
#include <math.h>

// Problem constants
#define T_TOKENS 25088      // 8 * 3136
#define DMODEL   768
#define NHEAD    12
#define DHEAD    64
#define FFDIM    3072
#define WS2      49
#define NWIN     512        // T_TOKENS / 49
#define D3       2304       // 3 * DMODEL

// ---------------- scratch (device globals; no allocation allowed) ----------------
__device__ __align__(128) float g_qkv[(size_t)T_TOKENS * D3];
__device__ __align__(128) float g_h[(size_t)T_TOKENS * DMODEL];
// bf16 hi/lo planes
__device__ __align__(128) unsigned short g_yh[(size_t)T_TOKENS * DMODEL];
__device__ __align__(128) unsigned short g_yl[(size_t)T_TOKENS * DMODEL];
__device__ __align__(128) unsigned short g_oh[(size_t)T_TOKENS * DMODEL];
__device__ __align__(128) unsigned short g_ol[(size_t)T_TOKENS * DMODEL];
__device__ __align__(128) unsigned short g_fh[(size_t)T_TOKENS * FFDIM];
__device__ __align__(128) unsigned short g_fl[(size_t)T_TOKENS * FFDIM];
__device__ __align__(128) unsigned short g_wh[(size_t)FFDIM * DMODEL];
__device__ __align__(128) unsigned short g_wl[(size_t)FFDIM * DMODEL];

// ---------------- bf16 helpers (pure bit ops) ----------------
__device__ __forceinline__ unsigned f2bf(float f)
{
    unsigned u = __float_as_uint(f);
    return (u + 0x7FFFu + ((u >> 16) & 1u)) >> 16;
}

__device__ __forceinline__ float bf2f(unsigned h)
{
    return __uint_as_float(h << 16);
}

// ---------------- weight split: fp32 -> hi/lo bf16 planes ----------------
__global__ __launch_bounds__(256) void split_kernel(
    const float* __restrict__ src, unsigned short* __restrict__ hi,
    unsigned short* __restrict__ lo)
{
    const int i = (blockIdx.x * 256 + threadIdx.x) * 4;
    float4 v = *(const float4*)(src + i);
    unsigned h0 = f2bf(v.x);
    unsigned h1 = f2bf(v.y);
    unsigned h2 = f2bf(v.z);
    unsigned h3 = f2bf(v.w);
    unsigned l0 = f2bf(v.x - bf2f(h0));
    unsigned l1 = f2bf(v.y - bf2f(h1));
    unsigned l2 = f2bf(v.z - bf2f(h2));
    unsigned l3 = f2bf(v.w - bf2f(h3));
    uint2 ph;
    ph.x = h0 | (h1 << 16);
    ph.y = h2 | (h3 << 16);
    *(uint2*)(hi + i) = ph;
    uint2 pl;
    pl.x = l0 | (l1 << 16);
    pl.y = l2 | (l3 << 16);
    *(uint2*)(lo + i) = pl;
}

// ---------------- LayerNorm: one block per token; writes hi/lo planes -------------
__global__ __launch_bounds__(256) void ln_kernel(
    const float* __restrict__ x, const float* __restrict__ w,
    const float* __restrict__ b, unsigned short* __restrict__ yh,
    unsigned short* __restrict__ yl)
{
    const int t = blockIdx.x;
    const float* xr = x + (size_t)t * DMODEL;
    unsigned short* yhr = yh + (size_t)t * DMODEL;
    unsigned short* ylr = yl + (size_t)t * DMODEL;
    const int tid = threadIdx.x;

    float v0 = xr[tid];
    float v1 = xr[tid + 256];
    float v2 = xr[tid + 512];
    float s = v0 + v1 + v2;
    float q = v0 * v0 + v1 * v1 + v2 * v2;

    #pragma unroll
    for (int off = 16; off > 0; off >>= 1) {
        s += __shfl_xor_sync(0xFFFFFFFFu, s, off);
        q += __shfl_xor_sync(0xFFFFFFFFu, q, off);
    }
    __shared__ float ss[8], sq[8];
    const int wid = tid >> 5, lid = tid & 31;
    if (lid == 0) { ss[wid] = s; sq[wid] = q; }
    __syncthreads();
    if (tid == 0) {
        float S = 0.f, Q = 0.f;
        #pragma unroll
        for (int i = 0; i < 8; i++) { S += ss[i]; Q += sq[i]; }
        float m = S * (1.0f / DMODEL);
        float var = Q * (1.0f / DMODEL) - m * m;
        ss[0] = m;
        sq[0] = rsqrtf(var + 1e-5f);
    }
    __syncthreads();
    const float m = ss[0], r = sq[0];
    float o0 = (v0 - m) * r * w[tid]       + b[tid];
    float o1 = (v1 - m) * r * w[tid + 256] + b[tid + 256];
    float o2 = (v2 - m) * r * w[tid + 512] + b[tid + 512];
    unsigned h0 = f2bf(o0);
    unsigned h1 = f2bf(o1);
    unsigned h2 = f2bf(o2);
    yhr[tid]       = (unsigned short)h0;
    yhr[tid + 256] = (unsigned short)h1;
    yhr[tid + 512] = (unsigned short)h2;
    ylr[tid]       = (unsigned short)f2bf(o0 - bf2f(h0));
    ylr[tid + 256] = (unsigned short)f2bf(o1 - bf2f(h1));
    ylr[tid + 512] = (unsigned short)f2bf(o2 - bf2f(h2));
}

// ---------------- Windowed attention (vectorized register-tiled) -------------------
// Padded to 56 rows; q/k/v row stride 68 floats (rows 16B-aligned); scores 56x56.
#define AP 56
#define QSTR 68
#define ATTN_SMEM ((3 * AP * QSTR + AP * AP) * 4)   // 58240 bytes

__global__ __launch_bounds__(256) void attn_kernel(
    const float* __restrict__ qkv, unsigned short* __restrict__ oh,
    unsigned short* __restrict__ ol)
{
    extern __shared__ float asmem[];
    float* sq = asmem;
    float* sk = sq + AP * QSTR;
    float* sv = sk + AP * QSTR;
    float* sp = sv + AP * QSTR;

    const int w  = blockIdx.x / NHEAD;
    const int hd = blockIdx.x % NHEAD;
    const int t0 = w * WS2;
    const int tid = threadIdx.x;

    // load q/k/v as float4 (56 rows x 16 float4)
    for (int i = tid; i < AP * 16; i += 256) {
        int r = i >> 4;
        int c4 = (i & 15) * 4;
        float4 q = make_float4(0.f, 0.f, 0.f, 0.f);
        float4 k = q;
        float4 v = q;
        if (r < WS2) {
            size_t base = (size_t)(t0 + r) * D3 + hd * DHEAD + c4;
            q = *(const float4*)(qkv + base);
            k = *(const float4*)(qkv + base + DMODEL);
            v = *(const float4*)(qkv + base + 2 * DMODEL);
        }
        *(float4*)(sq + r * QSTR + c4) = q;
        *(float4*)(sk + r * QSTR + c4) = k;
        *(float4*)(sv + r * QSTR + c4) = v;
    }
    __syncthreads();

    // phase 1: scores (4x4 per thread, float4 over d)
    {
        const int tj = tid % 14;
        const int ti = tid / 14;
        if (ti < 14) {
            float acc[4][4];
            #pragma unroll
            for (int i = 0; i < 4; i++)
                #pragma unroll
                for (int j = 0; j < 4; j++) acc[i][j] = 0.f;
            #pragma unroll 4
            for (int d = 0; d < DHEAD; d += 4) {
                float4 ra[4], rb[4];
                #pragma unroll
                for (int i = 0; i < 4; i++)
                    ra[i] = *(const float4*)(sq + (ti * 4 + i) * QSTR + d);
                #pragma unroll
                for (int j = 0; j < 4; j++)
                    rb[j] = *(const float4*)(sk + (tj * 4 + j) * QSTR + d);
                #pragma unroll
                for (int i = 0; i < 4; i++)
                    #pragma unroll
                    for (int j = 0; j < 4; j++) {
                        acc[i][j] = fmaf(ra[i].x, rb[j].x, acc[i][j]);
                        acc[i][j] = fmaf(ra[i].y, rb[j].y, acc[i][j]);
                        acc[i][j] = fmaf(ra[i].z, rb[j].z, acc[i][j]);
                        acc[i][j] = fmaf(ra[i].w, rb[j].w, acc[i][j]);
                    }
            }
            #pragma unroll
            for (int i = 0; i < 4; i++)
                #pragma unroll
                for (int j = 0; j < 4; j++)
                    sp[(ti * 4 + i) * AP + tj * 4 + j] = acc[i][j] * 0.125f;
        }
    }
    __syncthreads();

    // softmax: warp-parallel — one warp per row, lanes over columns
    {
        const int wrp = tid >> 5;
        const int ln = tid & 31;
        for (int r = wrp; r < WS2; r += 8) {
            float v1 = (ln < WS2)      ? sp[r * AP + ln]      : -1e30f;
            float v2 = (ln + 32 < WS2) ? sp[r * AP + 32 + ln] : -1e30f;
            float mx = fmaxf(v1, v2);
            #pragma unroll
            for (int off = 16; off > 0; off >>= 1)
                mx = fmaxf(mx, __shfl_xor_sync(0xFFFFFFFFu, mx, off));
            float e1 = (ln < WS2)      ? __expf(v1 - mx) : 0.f;
            float e2 = (ln + 32 < WS2) ? __expf(v2 - mx) : 0.f;
            float sum = e1 + e2;
            #pragma unroll
            for (int off = 16; off > 0; off >>= 1)
                sum += __shfl_xor_sync(0xFFFFFFFFu, sum, off);
            float inv = 1.0f / sum;
            if (ln < WS2)      sp[r * AP + ln]      = e1 * inv;
            if (ln + 32 < WS2) sp[r * AP + 32 + ln] = e2 * inv;
        }
    }
    __syncthreads();

    // phase 2: out = P @ V (4x4 per thread, float4 V loads)
    {
        const int tj = tid % 16;      // d block
        const int ti = tid / 16;      // row block
        if (ti < 13) {
            float acc[4][4];
            #pragma unroll
            for (int i = 0; i < 4; i++)
                #pragma unroll
                for (int j = 0; j < 4; j++) acc[i][j] = 0.f;
            #pragma unroll 7
            for (int kj = 0; kj < WS2; kj++) {
                float4 rb = *(const float4*)(sv + kj * QSTR + tj * 4);
                float ra[4];
                #pragma unroll
                for (int i = 0; i < 4; i++) ra[i] = sp[(ti * 4 + i) * AP + kj];
                #pragma unroll
                for (int i = 0; i < 4; i++) {
                    acc[i][0] = fmaf(ra[i], rb.x, acc[i][0]);
                    acc[i][1] = fmaf(ra[i], rb.y, acc[i][1]);
                    acc[i][2] = fmaf(ra[i], rb.z, acc[i][2]);
                    acc[i][3] = fmaf(ra[i], rb.w, acc[i][3]);
                }
            }
            #pragma unroll
            for (int i = 0; i < 4; i++) {
                const int qi = ti * 4 + i;
                if (qi < WS2) {
                    size_t obase = (size_t)(t0 + qi) * DMODEL + hd * DHEAD + tj * 4;
                    unsigned h0 = f2bf(acc[i][0]);
                    unsigned h1 = f2bf(acc[i][1]);
                    unsigned h2 = f2bf(acc[i][2]);
                    unsigned h3 = f2bf(acc[i][3]);
                    unsigned l0 = f2bf(acc[i][0] - bf2f(h0));
                    unsigned l1 = f2bf(acc[i][1] - bf2f(h1));
                    unsigned l2 = f2bf(acc[i][2] - bf2f(h2));
                    unsigned l3 = f2bf(acc[i][3] - bf2f(h3));
                    *(unsigned*)(oh + obase)     = h0 | (h1 << 16);
                    *(unsigned*)(oh + obase + 2) = h2 | (h3 << 16);
                    *(unsigned*)(ol + obase)     = l0 | (l1 << 16);
                    *(unsigned*)(ol + obase + 2) = l2 | (l3 << 16);
                }
            }
        }
    }
}

// ---------------- asm helpers ----------------
__device__ __forceinline__ unsigned smem_u32(const void* p)
{
    unsigned a;
    asm volatile("{ .reg .u64 t; cvta.to.shared.u64 t, %1; cvt.u32.u64 %0, t; }"
                 : "=r"(a) : "l"(p));
    return a;
}

__device__ __forceinline__ void ldsm4a(unsigned* r, unsigned addr)
{
    asm volatile("ldmatrix.sync.aligned.m8n8.x4.shared.b16 {%0,%1,%2,%3}, [%4];"
                 : "=r"(r[0]), "=r"(r[1]), "=r"(r[2]), "=r"(r[3]) : "r"(addr));
}

__device__ __forceinline__ void mma16816(float* c, const unsigned* a, unsigned b0, unsigned b1)
{
    asm volatile("mma.sync.aligned.m16n8k16.row.col.f32.bf16.bf16.f32 "
                 "{%0,%1,%2,%3}, {%4,%5,%6,%7}, {%8,%9}, {%0,%1,%2,%3};"
                 : "+f"(c[0]), "+f"(c[1]), "+f"(c[2]), "+f"(c[3])
                 : "r"(a[0]), "r"(a[1]), "r"(a[2]), "r"(a[3]), "r"(b0), "r"(b1));
}

__device__ __forceinline__ void cp16(unsigned dst, const void* src)
{
    asm volatile("cp.async.cg.shared.global [%0], [%1], 16;"
                 :: "r"(dst), "l"(src) : "memory");
}

__device__ __forceinline__ void cp_commit()
{
    asm volatile("cp.async.commit_group;" ::: "memory");
}

__device__ __forceinline__ void cp_wait1()
{
    asm volatile("cp.async.wait_group 1;" ::: "memory");
}

__device__ __forceinline__ void cp_wait0()
{
    asm volatile("cp.async.wait_group 0;" ::: "memory");
}

// ---------------- bf16x3 tensor-core GEMM (cp.async 2-stage pipeline) --------------
// C = act(A @ B^T + bias) (+ res); planes [M,K]/[N,K]; block 128x128, K-chunk 32 bf16.
// 8 warps, warp tile 64x32, mma.m16n8k16; smem rows 80B (64B data + 16B pad).
#define ROWB 80
#define PLANEB (128 * ROWB)          // 10240
#define STAGEB (4 * PLANEB)          // 40960
#define SMEMB  (2 * STAGEB)          // 81920

template <bool GELU, bool RES, bool SPLITOUT>
__global__ __launch_bounds__(256) void gemm_tc(
    const unsigned short* __restrict__ Ah, const unsigned short* __restrict__ Al,
    const unsigned short* __restrict__ Bh, const unsigned short* __restrict__ Bl,
    const float* __restrict__ bias,
    const float* __restrict__ res,
    float* __restrict__ C,
    unsigned short* __restrict__ Ch, unsigned short* __restrict__ Cl,
    int N, int K)
{
    extern __shared__ unsigned char dsm[];
    const unsigned sbase = smem_u32(dsm);
    const int tid = threadIdx.x;
    const int lane = tid & 31;
    const int wid = tid >> 5;
    const int wm = wid & 1;
    const int wn = wid >> 1;
    const int bm = blockIdx.y * 128;
    const int bn = blockIdx.x * 128;

    float acc[4][4][4];
    #pragma unroll
    for (int i = 0; i < 4; i++)
        #pragma unroll
        for (int j = 0; j < 4; j++)
            #pragma unroll
            for (int k = 0; k < 4; k++) acc[i][j][k] = 0.f;

    // loader: rows r0 and r0+64, 16B chunk ch (8 bf16) of the 64B k-chunk row
    const int r0 = tid >> 2;
    const int ch = tid & 3;
    const unsigned short* gAh = Ah + (size_t)(bm + r0) * K + ch * 8;
    const unsigned short* gAl = Al + (size_t)(bm + r0) * K + ch * 8;
    const unsigned short* gBh = Bh + (size_t)(bn + r0) * K + ch * 8;
    const unsigned short* gBl = Bl + (size_t)(bn + r0) * K + ch * 8;
    const size_t rstep = (size_t)64 * K;
    const unsigned drow0 = r0 * ROWB + ch * 16;
    const unsigned drow1 = (r0 + 64) * ROWB + ch * 16;
    const int nkc = K / 32;

    // prologue: stage 0, chunk 0
    {
        const unsigned st = sbase;
        cp16(st + drow0,              gAh);
        cp16(st + drow1,              gAh + rstep);
        cp16(st + PLANEB + drow0,     gAl);
        cp16(st + PLANEB + drow1,     gAl + rstep);
        cp16(st + 2 * PLANEB + drow0, gBh);
        cp16(st + 2 * PLANEB + drow1, gBh + rstep);
        cp16(st + 3 * PLANEB + drow0, gBl);
        cp16(st + 3 * PLANEB + drow1, gBl + rstep);
        cp_commit();
    }

    for (int kc = 0; kc < nkc; kc++) {
        if (kc + 1 < nkc) {
            const unsigned st = sbase + ((kc + 1) & 1) * STAGEB;
            const int ko = (kc + 1) * 32;
            cp16(st + drow0,              gAh + ko);
            cp16(st + drow1,              gAh + ko + rstep);
            cp16(st + PLANEB + drow0,     gAl + ko);
            cp16(st + PLANEB + drow1,     gAl + ko + rstep);
            cp16(st + 2 * PLANEB + drow0, gBh + ko);
            cp16(st + 2 * PLANEB + drow1, gBh + ko + rstep);
            cp16(st + 3 * PLANEB + drow0, gBl + ko);
            cp16(st + 3 * PLANEB + drow1, gBl + ko + rstep);
            cp_commit();
            cp_wait1();
        } else {
            cp_wait0();
        }
        __syncthreads();

        const unsigned st = sbase + (kc & 1) * STAGEB;
        #pragma unroll
        for (int ks = 0; ks < 2; ks++) {
            const unsigned abase = st + (wm * 64 + (lane & 15)) * ROWB
                                   + ks * 32 + ((lane >> 4) << 4);
            const unsigned bbase = st + 2 * PLANEB + (wn * 32 + (lane & 15)) * ROWB
                                   + ks * 32 + ((lane >> 4) << 4);
            unsigned ah[4][4], al[4][4];
            #pragma unroll
            for (int mi = 0; mi < 4; mi++) {
                ldsm4a(ah[mi], abase + mi * 16 * ROWB);
                ldsm4a(al[mi], abase + PLANEB + mi * 16 * ROWB);
            }
            unsigned bh[2][4], bl[2][4];
            #pragma unroll
            for (int nj = 0; nj < 2; nj++) {
                ldsm4a(bh[nj], bbase + nj * 16 * ROWB);
                ldsm4a(bl[nj], bbase + PLANEB + nj * 16 * ROWB);
            }
            // product-major ordering: 16 independent MMAs between acc reuses
            #pragma unroll
            for (int mi = 0; mi < 4; mi++)
                #pragma unroll
                for (int ni = 0; ni < 4; ni++)
                    mma16816(acc[mi][ni], ah[mi], bh[ni >> 1][ni & 1],
                             bh[ni >> 1][(ni & 1) + 2]);            // Ah*Bh
            #pragma unroll
            for (int mi = 0; mi < 4; mi++)
                #pragma unroll
                for (int ni = 0; ni < 4; ni++)
                    mma16816(acc[mi][ni], ah[mi], bl[ni >> 1][ni & 1],
                             bl[ni >> 1][(ni & 1) + 2]);            // Ah*Bl
            #pragma unroll
            for (int mi = 0; mi < 4; mi++)
                #pragma unroll
                for (int ni = 0; ni < 4; ni++)
                    mma16816(acc[mi][ni], al[mi], bh[ni >> 1][ni & 1],
                             bh[ni >> 1][(ni & 1) + 2]);            // Al*Bh
        }
        __syncthreads();
    }

    // epilogue
    #pragma unroll
    for (int mi = 0; mi < 4; mi++) {
        #pragma unroll
        for (int ni = 0; ni < 4; ni++) {
            const int col = bn + wn * 32 + ni * 8 + (lane & 3) * 2;
            const float bs0 = bias[col];
            const float bs1 = bias[col + 1];
            #pragma unroll
            for (int half = 0; half < 2; half++) {
                const int row = bm + wm * 64 + mi * 16 + (lane >> 2) + half * 8;
                float v0 = acc[mi][ni][half * 2 + 0] + bs0;
                float v1 = acc[mi][ni][half * 2 + 1] + bs1;
                if (GELU) {
                    v0 = 0.5f * v0 * (1.0f + erff(v0 * 0.70710678118654752f));
                    v1 = 0.5f * v1 * (1.0f + erff(v1 * 0.70710678118654752f));
                }
                if (RES) {
                    float2 r2 = *(const float2*)(res + (size_t)row * N + col);
                    v0 += r2.x;
                    v1 += r2.y;
                }
                if (SPLITOUT) {
                    unsigned h0 = f2bf(v0);
                    unsigned h1 = f2bf(v1);
                    unsigned l0 = f2bf(v0 - bf2f(h0));
                    unsigned l1 = f2bf(v1 - bf2f(h1));
                    *(unsigned*)(Ch + (size_t)row * N + col) = h0 | (h1 << 16);
                    *(unsigned*)(Cl + (size_t)row * N + col) = l0 | (l1 << 16);
                } else {
                    float2 o2;
                    o2.x = v0;
                    o2.y = v1;
                    *(float2*)(C + (size_t)row * N + col) = o2;
                }
            }
        }
    }
}

// ---------------- host-side launch ----------------
extern "C" void kernel_launch(void* const* d_in, const int* in_sizes, int n_in,
                              void* d_out, int out_size)
{
    const float* x     = (const float*)d_in[0];
    const float* Wqkv  = (const float*)d_in[1];
    const float* bqkv  = (const float*)d_in[2];
    const float* Wo    = (const float*)d_in[3];
    const float* bo    = (const float*)d_in[4];
    const float* ln1_w = (const float*)d_in[5];
    const float* ln1_b = (const float*)d_in[6];
    const float* W1    = (const float*)d_in[7];
    const float* b1    = (const float*)d_in[8];
    const float* W2    = (const float*)d_in[9];
    const float* b2    = (const float*)d_in[10];
    const float* ln2_w = (const float*)d_in[11];
    const float* ln2_b = (const float*)d_in[12];
    float* out = (float*)d_out;

    static float *p_qkv = nullptr, *p_h = nullptr;
    static unsigned short *p_yh = nullptr, *p_yl = nullptr, *p_oh = nullptr, *p_ol = nullptr;
    static unsigned short *p_fh = nullptr, *p_fl = nullptr, *p_wh = nullptr, *p_wl = nullptr;
    if (!p_qkv) {
        cudaGetSymbolAddress((void**)&p_qkv, g_qkv);
        cudaGetSymbolAddress((void**)&p_h,   g_h);
        cudaGetSymbolAddress((void**)&p_yh,  g_yh);
        cudaGetSymbolAddress((void**)&p_yl,  g_yl);
        cudaGetSymbolAddress((void**)&p_oh,  g_oh);
        cudaGetSymbolAddress((void**)&p_ol,  g_ol);
        cudaGetSymbolAddress((void**)&p_fh,  g_fh);
        cudaGetSymbolAddress((void**)&p_fl,  g_fl);
        cudaGetSymbolAddress((void**)&p_wh,  g_wh);
        cudaGetSymbolAddress((void**)&p_wl,  g_wl);
        cudaFuncSetAttribute(gemm_tc<false, false, false>,
                             cudaFuncAttributeMaxDynamicSharedMemorySize, SMEMB);
        cudaFuncSetAttribute(gemm_tc<false, true, false>,
                             cudaFuncAttributeMaxDynamicSharedMemorySize, SMEMB);
        cudaFuncSetAttribute(gemm_tc<true, false, true>,
                             cudaFuncAttributeMaxDynamicSharedMemorySize, SMEMB);
        cudaFuncSetAttribute(attn_kernel,
                             cudaFuncAttributeMaxDynamicSharedMemorySize, ATTN_SMEM);
    }

    const dim3 blk(256);
    const dim3 grid_qkv(D3 / 128,     T_TOKENS / 128);
    const dim3 grid_d  (DMODEL / 128, T_TOKENS / 128);
    const dim3 grid_ff (FFDIM / 128,  T_TOKENS / 128);

    for (int l = 0; l < 2; l++) {
        const float* hin  = (l == 0) ? x : p_h;
        float* hout2 = (l == 1) ? out : p_h;   // last FFN GEMM writes final output

        // pre-norm attention
        ln_kernel<<<T_TOKENS, blk>>>(hin, ln1_w + l * DMODEL, ln1_b + l * DMODEL, p_yh, p_yl);
        split_kernel<<<(D3 * DMODEL) / 1024, blk>>>(Wqkv + (size_t)l * D3 * DMODEL, p_wh, p_wl);
        gemm_tc<false, false, false><<<grid_qkv, blk, SMEMB>>>(
            p_yh, p_yl, p_wh, p_wl, bqkv + (size_t)l * D3,
            nullptr, p_qkv, nullptr, nullptr, D3, DMODEL);
        attn_kernel<<<NWIN * NHEAD, blk, ATTN_SMEM>>>(p_qkv, p_oh, p_ol);
        split_kernel<<<(DMODEL * DMODEL) / 1024, blk>>>(Wo + (size_t)l * DMODEL * DMODEL, p_wh, p_wl);
        gemm_tc<false, true, false><<<grid_d, blk, SMEMB>>>(
            p_oh, p_ol, p_wh, p_wl, bo + (size_t)l * DMODEL,
            hin, p_h, nullptr, nullptr, DMODEL, DMODEL);

        // pre-norm FFN
        ln_kernel<<<T_TOKENS, blk>>>(p_h, ln2_w + l * DMODEL, ln2_b + l * DMODEL, p_yh, p_yl);
        split_kernel<<<(FFDIM * DMODEL) / 1024, blk>>>(W1 + (size_t)l * FFDIM * DMODEL, p_wh, p_wl);
        gemm_tc<true, false, true><<<grid_ff, blk, SMEMB>>>(
            p_yh, p_yl, p_wh, p_wl, b1 + (size_t)l * FFDIM,
            nullptr, nullptr, p_fh, p_fl, FFDIM, DMODEL);
        split_kernel<<<(DMODEL * FFDIM) / 1024, blk>>>(W2 + (size_t)l * DMODEL * FFDIM, p_wh, p_wl);
        gemm_tc<false, true, false><<<grid_d, blk, SMEMB>>>(
            p_fh, p_fl, p_wh, p_wl, b2 + (size_t)l * DMODEL,
            p_h, hout2, nullptr, nullptr, DMODEL, FFDIM);
    }
    (void)in_sizes; (void)n_in; (void)out_size;
}

// round 12
// speedup vs baseline: 6.1425x; 2.0542x over previous
#include <cuda_runtime.h>
#include <math.h>

// Problem constants
#define T_TOKENS 25088      // 8 * 3136
#define DMODEL   768
#define NHEAD    12
#define DHEAD    64
#define FFDIM    3072
#define WS2      49
#define NWIN     512        // T_TOKENS / 49
#define D3       2304       // 3 * DMODEL

// ---------------- scratch (device globals; no allocation allowed) ----------------
__device__ __align__(128) float g_qkv[(size_t)T_TOKENS * D3];
__device__ __align__(128) float g_h[(size_t)T_TOKENS * DMODEL];
// fp16 planes
__device__ __align__(128) unsigned short g_yh[(size_t)T_TOKENS * DMODEL];
__device__ __align__(128) unsigned short g_oh[(size_t)T_TOKENS * DMODEL];
__device__ __align__(128) unsigned short g_fh[(size_t)T_TOKENS * FFDIM];
__device__ __align__(128) unsigned short g_wh[(size_t)FFDIM * DMODEL];

// ---------------- fp16 helper (inline PTX; no cuda_fp16.h) ----------------
__device__ __forceinline__ unsigned short f2h(float f)
{
    unsigned short h;
    asm("cvt.rn.f16.f32 %0, %1;" : "=h"(h) : "f"(f));
    return h;
}

// ---------------- weight convert: fp32 -> fp16 plane ----------------
__global__ __launch_bounds__(256) void cvt_kernel(
    const float* __restrict__ src, unsigned short* __restrict__ dst)
{
    const int i = (blockIdx.x * 256 + threadIdx.x) * 4;
    float4 v = *(const float4*)(src + i);
    unsigned p0 = (unsigned)f2h(v.x) | ((unsigned)f2h(v.y) << 16);
    unsigned p1 = (unsigned)f2h(v.z) | ((unsigned)f2h(v.w) << 16);
    uint2 o;
    o.x = p0;
    o.y = p1;
    *(uint2*)(dst + i) = o;
}

// ---------------- LayerNorm: one block per token; writes fp16 plane ---------------
__global__ __launch_bounds__(256) void ln_kernel(
    const float* __restrict__ x, const float* __restrict__ w,
    const float* __restrict__ b, unsigned short* __restrict__ yh)
{
    const int t = blockIdx.x;
    const float* xr = x + (size_t)t * DMODEL;
    unsigned short* yhr = yh + (size_t)t * DMODEL;
    const int tid = threadIdx.x;

    float v0 = xr[tid];
    float v1 = xr[tid + 256];
    float v2 = xr[tid + 512];
    float s = v0 + v1 + v2;
    float q = v0 * v0 + v1 * v1 + v2 * v2;

    #pragma unroll
    for (int off = 16; off > 0; off >>= 1) {
        s += __shfl_xor_sync(0xFFFFFFFFu, s, off);
        q += __shfl_xor_sync(0xFFFFFFFFu, q, off);
    }
    __shared__ float ss[8], sq[8];
    const int wid = tid >> 5, lid = tid & 31;
    if (lid == 0) { ss[wid] = s; sq[wid] = q; }
    __syncthreads();
    if (tid == 0) {
        float S = 0.f, Q = 0.f;
        #pragma unroll
        for (int i = 0; i < 8; i++) { S += ss[i]; Q += sq[i]; }
        float m = S * (1.0f / DMODEL);
        float var = Q * (1.0f / DMODEL) - m * m;
        ss[0] = m;
        sq[0] = rsqrtf(var + 1e-5f);
    }
    __syncthreads();
    const float m = ss[0], r = sq[0];
    float o0 = (v0 - m) * r * w[tid]       + b[tid];
    float o1 = (v1 - m) * r * w[tid + 256] + b[tid + 256];
    float o2 = (v2 - m) * r * w[tid + 512] + b[tid + 512];
    yhr[tid]       = f2h(o0);
    yhr[tid + 256] = f2h(o1);
    yhr[tid + 512] = f2h(o2);
}

// ---------------- Windowed attention (vectorized register-tiled) -------------------
// Padded to 56 rows; q/k/v row stride 68 floats (rows 16B-aligned); scores 56x56.
#define AP 56
#define QSTR 68
#define ATTN_SMEM ((3 * AP * QSTR + AP * AP) * 4)   // 58240 bytes

__global__ __launch_bounds__(256) void attn_kernel(
    const float* __restrict__ qkv, unsigned short* __restrict__ oh)
{
    extern __shared__ float asmem[];
    float* sq = asmem;
    float* sk = sq + AP * QSTR;
    float* sv = sk + AP * QSTR;
    float* sp = sv + AP * QSTR;

    const int w  = blockIdx.x / NHEAD;
    const int hd = blockIdx.x % NHEAD;
    const int t0 = w * WS2;
    const int tid = threadIdx.x;

    // load q/k/v as float4 (56 rows x 16 float4)
    for (int i = tid; i < AP * 16; i += 256) {
        int r = i >> 4;
        int c4 = (i & 15) * 4;
        float4 q = make_float4(0.f, 0.f, 0.f, 0.f);
        float4 k = q;
        float4 v = q;
        if (r < WS2) {
            size_t base = (size_t)(t0 + r) * D3 + hd * DHEAD + c4;
            q = *(const float4*)(qkv + base);
            k = *(const float4*)(qkv + base + DMODEL);
            v = *(const float4*)(qkv + base + 2 * DMODEL);
        }
        *(float4*)(sq + r * QSTR + c4) = q;
        *(float4*)(sk + r * QSTR + c4) = k;
        *(float4*)(sv + r * QSTR + c4) = v;
    }
    __syncthreads();

    // phase 1: scores (4x4 per thread, float4 over d)
    {
        const int tj = tid % 14;
        const int ti = tid / 14;
        if (ti < 14) {
            float acc[4][4];
            #pragma unroll
            for (int i = 0; i < 4; i++)
                #pragma unroll
                for (int j = 0; j < 4; j++) acc[i][j] = 0.f;
            #pragma unroll 4
            for (int d = 0; d < DHEAD; d += 4) {
                float4 ra[4], rb[4];
                #pragma unroll
                for (int i = 0; i < 4; i++)
                    ra[i] = *(const float4*)(sq + (ti * 4 + i) * QSTR + d);
                #pragma unroll
                for (int j = 0; j < 4; j++)
                    rb[j] = *(const float4*)(sk + (tj * 4 + j) * QSTR + d);
                #pragma unroll
                for (int i = 0; i < 4; i++)
                    #pragma unroll
                    for (int j = 0; j < 4; j++) {
                        acc[i][j] = fmaf(ra[i].x, rb[j].x, acc[i][j]);
                        acc[i][j] = fmaf(ra[i].y, rb[j].y, acc[i][j]);
                        acc[i][j] = fmaf(ra[i].z, rb[j].z, acc[i][j]);
                        acc[i][j] = fmaf(ra[i].w, rb[j].w, acc[i][j]);
                    }
            }
            #pragma unroll
            for (int i = 0; i < 4; i++)
                #pragma unroll
                for (int j = 0; j < 4; j++)
                    sp[(ti * 4 + i) * AP + tj * 4 + j] = acc[i][j] * 0.125f;
        }
    }
    __syncthreads();

    // softmax: warp-parallel — one warp per row, lanes over columns
    {
        const int wrp = tid >> 5;
        const int ln = tid & 31;
        for (int r = wrp; r < WS2; r += 8) {
            float v1 = (ln < WS2)      ? sp[r * AP + ln]      : -1e30f;
            float v2 = (ln + 32 < WS2) ? sp[r * AP + 32 + ln] : -1e30f;
            float mx = fmaxf(v1, v2);
            #pragma unroll
            for (int off = 16; off > 0; off >>= 1)
                mx = fmaxf(mx, __shfl_xor_sync(0xFFFFFFFFu, mx, off));
            float e1 = (ln < WS2)      ? __expf(v1 - mx) : 0.f;
            float e2 = (ln + 32 < WS2) ? __expf(v2 - mx) : 0.f;
            float sum = e1 + e2;
            #pragma unroll
            for (int off = 16; off > 0; off >>= 1)
                sum += __shfl_xor_sync(0xFFFFFFFFu, sum, off);
            float inv = 1.0f / sum;
            if (ln < WS2)      sp[r * AP + ln]      = e1 * inv;
            if (ln + 32 < WS2) sp[r * AP + 32 + ln] = e2 * inv;
        }
    }
    __syncthreads();

    // phase 2: out = P @ V (4x4 per thread, float4 V loads), fp16 output
    {
        const int tj = tid % 16;      // d block
        const int ti = tid / 16;      // row block
        if (ti < 13) {
            float acc[4][4];
            #pragma unroll
            for (int i = 0; i < 4; i++)
                #pragma unroll
                for (int j = 0; j < 4; j++) acc[i][j] = 0.f;
            #pragma unroll 7
            for (int kj = 0; kj < WS2; kj++) {
                float4 rb = *(const float4*)(sv + kj * QSTR + tj * 4);
                float ra[4];
                #pragma unroll
                for (int i = 0; i < 4; i++) ra[i] = sp[(ti * 4 + i) * AP + kj];
                #pragma unroll
                for (int i = 0; i < 4; i++) {
                    acc[i][0] = fmaf(ra[i], rb.x, acc[i][0]);
                    acc[i][1] = fmaf(ra[i], rb.y, acc[i][1]);
                    acc[i][2] = fmaf(ra[i], rb.z, acc[i][2]);
                    acc[i][3] = fmaf(ra[i], rb.w, acc[i][3]);
                }
            }
            #pragma unroll
            for (int i = 0; i < 4; i++) {
                const int qi = ti * 4 + i;
                if (qi < WS2) {
                    size_t obase = (size_t)(t0 + qi) * DMODEL + hd * DHEAD + tj * 4;
                    unsigned p0 = (unsigned)f2h(acc[i][0]) | ((unsigned)f2h(acc[i][1]) << 16);
                    unsigned p1 = (unsigned)f2h(acc[i][2]) | ((unsigned)f2h(acc[i][3]) << 16);
                    *(unsigned*)(oh + obase)     = p0;
                    *(unsigned*)(oh + obase + 2) = p1;
                }
            }
        }
    }
}

// ---------------- asm helpers ----------------
__device__ __forceinline__ unsigned smem_u32(const void* p)
{
    unsigned a;
    asm volatile("{ .reg .u64 t; cvta.to.shared.u64 t, %1; cvt.u32.u64 %0, t; }"
                 : "=r"(a) : "l"(p));
    return a;
}

__device__ __forceinline__ void ldsm4a(unsigned* r, unsigned addr)
{
    asm volatile("ldmatrix.sync.aligned.m8n8.x4.shared.b16 {%0,%1,%2,%3}, [%4];"
                 : "=r"(r[0]), "=r"(r[1]), "=r"(r[2]), "=r"(r[3]) : "r"(addr));
}

__device__ __forceinline__ void mma_f16(float* c, const unsigned* a, unsigned b0, unsigned b1)
{
    asm volatile("mma.sync.aligned.m16n8k16.row.col.f32.f16.f16.f32 "
                 "{%0,%1,%2,%3}, {%4,%5,%6,%7}, {%8,%9}, {%0,%1,%2,%3};"
                 : "+f"(c[0]), "+f"(c[1]), "+f"(c[2]), "+f"(c[3])
                 : "r"(a[0]), "r"(a[1]), "r"(a[2]), "r"(a[3]), "r"(b0), "r"(b1));
}

__device__ __forceinline__ void cp16(unsigned dst, const void* src)
{
    asm volatile("cp.async.cg.shared.global [%0], [%1], 16;"
                 :: "r"(dst), "l"(src) : "memory");
}

__device__ __forceinline__ void cp_commit()
{
    asm volatile("cp.async.commit_group;" ::: "memory");
}

__device__ __forceinline__ void cp_wait1()
{
    asm volatile("cp.async.wait_group 1;" ::: "memory");
}

__device__ __forceinline__ void cp_wait0()
{
    asm volatile("cp.async.wait_group 0;" ::: "memory");
}

// ---------------- fp16 tensor-core GEMM (cp.async 2-stage pipeline) ---------------
// C = act(A @ B^T + bias) (+ res); fp16 A [M,K], B [N,K]; block 128x128, K-chunk 32.
// 8 warps, warp tile 64x32, mma.m16n8k16.f16; smem rows 80B (64B data + 16B pad).
#define ROWB 80
#define PLANEB (128 * ROWB)          // 10240
#define STAGEB (2 * PLANEB)          // 20480 (A plane + B plane)
#define SMEMB  (2 * STAGEB)          // 40960

template <bool GELU, bool RES, bool HALFOUT>
__global__ __launch_bounds__(256) void gemm_f16(
    const unsigned short* __restrict__ Ah,
    const unsigned short* __restrict__ Bh,
    const float* __restrict__ bias,
    const float* __restrict__ res,
    float* __restrict__ C,
    unsigned short* __restrict__ Ch,
    int N, int K)
{
    extern __shared__ unsigned char dsm[];
    const unsigned sbase = smem_u32(dsm);
    const int tid = threadIdx.x;
    const int lane = tid & 31;
    const int wid = tid >> 5;
    const int wm = wid & 1;
    const int wn = wid >> 1;
    const int bm = blockIdx.y * 128;
    const int bn = blockIdx.x * 128;

    float acc[4][4][4];
    #pragma unroll
    for (int i = 0; i < 4; i++)
        #pragma unroll
        for (int j = 0; j < 4; j++)
            #pragma unroll
            for (int k = 0; k < 4; k++) acc[i][j][k] = 0.f;

    // loader: rows r0 and r0+64, 16B chunk ch (8 halves) of the 64B k-chunk row
    const int r0 = tid >> 2;
    const int ch = tid & 3;
    const unsigned short* gA = Ah + (size_t)(bm + r0) * K + ch * 8;
    const unsigned short* gB = Bh + (size_t)(bn + r0) * K + ch * 8;
    const size_t rstep = (size_t)64 * K;
    const unsigned drow0 = r0 * ROWB + ch * 16;
    const unsigned drow1 = (r0 + 64) * ROWB + ch * 16;
    const int nkc = K / 32;

    // prologue: stage 0, chunk 0
    {
        const unsigned st = sbase;
        cp16(st + drow0,          gA);
        cp16(st + drow1,          gA + rstep);
        cp16(st + PLANEB + drow0, gB);
        cp16(st + PLANEB + drow1, gB + rstep);
        cp_commit();
    }

    for (int kc = 0; kc < nkc; kc++) {
        if (kc + 1 < nkc) {
            const unsigned st = sbase + ((kc + 1) & 1) * STAGEB;
            const int ko = (kc + 1) * 32;
            cp16(st + drow0,          gA + ko);
            cp16(st + drow1,          gA + ko + rstep);
            cp16(st + PLANEB + drow0, gB + ko);
            cp16(st + PLANEB + drow1, gB + ko + rstep);
            cp_commit();
            cp_wait1();
        } else {
            cp_wait0();
        }
        __syncthreads();

        const unsigned st = sbase + (kc & 1) * STAGEB;
        #pragma unroll
        for (int ks = 0; ks < 2; ks++) {
            const unsigned abase = st + (wm * 64 + (lane & 15)) * ROWB
                                   + ks * 32 + ((lane >> 4) << 4);
            const unsigned bbase = st + PLANEB + (wn * 32 + (lane & 15)) * ROWB
                                   + ks * 32 + ((lane >> 4) << 4);
            unsigned ah[4][4];
            #pragma unroll
            for (int mi = 0; mi < 4; mi++)
                ldsm4a(ah[mi], abase + mi * 16 * ROWB);
            unsigned bh[2][4];
            #pragma unroll
            for (int nj = 0; nj < 2; nj++)
                ldsm4a(bh[nj], bbase + nj * 16 * ROWB);
            #pragma unroll
            for (int mi = 0; mi < 4; mi++)
                #pragma unroll
                for (int ni = 0; ni < 4; ni++)
                    mma_f16(acc[mi][ni], ah[mi], bh[ni >> 1][ni & 1],
                            bh[ni >> 1][(ni & 1) + 2]);
        }
        __syncthreads();
    }

    // epilogue
    #pragma unroll
    for (int mi = 0; mi < 4; mi++) {
        #pragma unroll
        for (int ni = 0; ni < 4; ni++) {
            const int col = bn + wn * 32 + ni * 8 + (lane & 3) * 2;
            const float bs0 = bias[col];
            const float bs1 = bias[col + 1];
            #pragma unroll
            for (int half = 0; half < 2; half++) {
                const int row = bm + wm * 64 + mi * 16 + (lane >> 2) + half * 8;
                float v0 = acc[mi][ni][half * 2 + 0] + bs0;
                float v1 = acc[mi][ni][half * 2 + 1] + bs1;
                if (GELU) {
                    v0 = 0.5f * v0 * (1.0f + erff(v0 * 0.70710678118654752f));
                    v1 = 0.5f * v1 * (1.0f + erff(v1 * 0.70710678118654752f));
                }
                if (RES) {
                    float2 r2 = *(const float2*)(res + (size_t)row * N + col);
                    v0 += r2.x;
                    v1 += r2.y;
                }
                if (HALFOUT) {
                    unsigned p = (unsigned)f2h(v0) | ((unsigned)f2h(v1) << 16);
                    *(unsigned*)(Ch + (size_t)row * N + col) = p;
                } else {
                    float2 o2;
                    o2.x = v0;
                    o2.y = v1;
                    *(float2*)(C + (size_t)row * N + col) = o2;
                }
            }
        }
    }
}

// ---------------- host-side launch ----------------
extern "C" void kernel_launch(void* const* d_in, const int* in_sizes, int n_in,
                              void* d_out, int out_size)
{
    const float* x     = (const float*)d_in[0];
    const float* Wqkv  = (const float*)d_in[1];
    const float* bqkv  = (const float*)d_in[2];
    const float* Wo    = (const float*)d_in[3];
    const float* bo    = (const float*)d_in[4];
    const float* ln1_w = (const float*)d_in[5];
    const float* ln1_b = (const float*)d_in[6];
    const float* W1    = (const float*)d_in[7];
    const float* b1    = (const float*)d_in[8];
    const float* W2    = (const float*)d_in[9];
    const float* b2    = (const float*)d_in[10];
    const float* ln2_w = (const float*)d_in[11];
    const float* ln2_b = (const float*)d_in[12];
    float* out = (float*)d_out;

    static float *p_qkv = nullptr, *p_h = nullptr;
    static unsigned short *p_yh = nullptr, *p_oh = nullptr, *p_fh = nullptr, *p_wh = nullptr;
    if (!p_qkv) {
        cudaGetSymbolAddress((void**)&p_qkv, g_qkv);
        cudaGetSymbolAddress((void**)&p_h,   g_h);
        cudaGetSymbolAddress((void**)&p_yh,  g_yh);
        cudaGetSymbolAddress((void**)&p_oh,  g_oh);
        cudaGetSymbolAddress((void**)&p_fh,  g_fh);
        cudaGetSymbolAddress((void**)&p_wh,  g_wh);
        cudaFuncSetAttribute(gemm_f16<false, false, false>,
                             cudaFuncAttributeMaxDynamicSharedMemorySize, SMEMB);
        cudaFuncSetAttribute(gemm_f16<false, true, false>,
                             cudaFuncAttributeMaxDynamicSharedMemorySize, SMEMB);
        cudaFuncSetAttribute(gemm_f16<true, false, true>,
                             cudaFuncAttributeMaxDynamicSharedMemorySize, SMEMB);
        cudaFuncSetAttribute(attn_kernel,
                             cudaFuncAttributeMaxDynamicSharedMemorySize, ATTN_SMEM);
    }

    const dim3 blk(256);
    const dim3 grid_qkv(D3 / 128,     T_TOKENS / 128);
    const dim3 grid_d  (DMODEL / 128, T_TOKENS / 128);
    const dim3 grid_ff (FFDIM / 128,  T_TOKENS / 128);

    for (int l = 0; l < 2; l++) {
        const float* hin  = (l == 0) ? x : p_h;
        float* hout2 = (l == 1) ? out : p_h;   // last FFN GEMM writes final output

        // pre-norm attention
        ln_kernel<<<T_TOKENS, blk>>>(hin, ln1_w + l * DMODEL, ln1_b + l * DMODEL, p_yh);
        cvt_kernel<<<(D3 * DMODEL) / 1024, blk>>>(Wqkv + (size_t)l * D3 * DMODEL, p_wh);
        gemm_f16<false, false, false><<<grid_qkv, blk, SMEMB>>>(
            p_yh, p_wh, bqkv + (size_t)l * D3,
            nullptr, p_qkv, nullptr, D3, DMODEL);
        attn_kernel<<<NWIN * NHEAD, blk, ATTN_SMEM>>>(p_qkv, p_oh);
        cvt_kernel<<<(DMODEL * DMODEL) / 1024, blk>>>(Wo + (size_t)l * DMODEL * DMODEL, p_wh);
        gemm_f16<false, true, false><<<grid_d, blk, SMEMB>>>(
            p_oh, p_wh, bo + (size_t)l * DMODEL,
            hin, p_h, nullptr, DMODEL, DMODEL);

        // pre-norm FFN
        ln_kernel<<<T_TOKENS, blk>>>(p_h, ln2_w + l * DMODEL, ln2_b + l * DMODEL, p_yh);
        cvt_kernel<<<(FFDIM * DMODEL) / 1024, blk>>>(W1 + (size_t)l * FFDIM * DMODEL, p_wh);
        gemm_f16<true, false, true><<<grid_ff, blk, SMEMB>>>(
            p_yh, p_wh, b1 + (size_t)l * FFDIM,
            nullptr, nullptr, p_fh, FFDIM, DMODEL);
        cvt_kernel<<<(DMODEL * FFDIM) / 1024, blk>>>(W2 + (size_t)l * DMODEL * FFDIM, p_wh);
        gemm_f16<false, true, false><<<grid_d, blk, SMEMB>>>(
            p_fh, p_wh, b2 + (size_t)l * DMODEL,
            p_h, hout2, nullptr, DMODEL, FFDIM);
    }
    (void)in_sizes; (void)n_in; (void)out_size;
}

// round 13
// speedup vs baseline: 6.4339x; 1.0474x over previous
#include <cuda_runtime.h>
#include <math.h>

// Problem constants
#define T_TOKENS 25088      // 8 * 3136
#define DMODEL   768
#define NHEAD    12
#define DHEAD    64
#define FFDIM    3072
#define WS2      49
#define NWIN     512        // T_TOKENS / 49
#define D3       2304       // 3 * DMODEL

// ---------------- scratch (device globals; no allocation allowed) ----------------
__device__ __align__(128) float g_h[(size_t)T_TOKENS * DMODEL];
// fp16 planes
__device__ __align__(128) unsigned short g_qkvh[(size_t)T_TOKENS * D3];
__device__ __align__(128) unsigned short g_yh[(size_t)T_TOKENS * DMODEL];
__device__ __align__(128) unsigned short g_oh[(size_t)T_TOKENS * DMODEL];
__device__ __align__(128) unsigned short g_fh[(size_t)T_TOKENS * FFDIM];
__device__ __align__(128) unsigned short g_wh[(size_t)FFDIM * DMODEL];

// ---------------- fp16 helpers (inline PTX; no cuda_fp16.h) ----------------
__device__ __forceinline__ unsigned short f2h(float f)
{
    unsigned short h;
    asm("cvt.rn.f16.f32 %0, %1;" : "=h"(h) : "f"(f));
    return h;
}

__device__ __forceinline__ float h2f(unsigned short h)
{
    float f;
    asm("cvt.f32.f16 %0, %1;" : "=f"(f) : "h"(h));
    return f;
}

// ---------------- weight convert: fp32 -> fp16 plane ----------------
__global__ __launch_bounds__(256) void cvt_kernel(
    const float* __restrict__ src, unsigned short* __restrict__ dst)
{
    const int i = (blockIdx.x * 256 + threadIdx.x) * 4;
    float4 v = *(const float4*)(src + i);
    unsigned p0 = (unsigned)f2h(v.x) | ((unsigned)f2h(v.y) << 16);
    unsigned p1 = (unsigned)f2h(v.z) | ((unsigned)f2h(v.w) << 16);
    uint2 o;
    o.x = p0;
    o.y = p1;
    *(uint2*)(dst + i) = o;
}

// ---------------- LayerNorm: one block per token; writes fp16 plane ---------------
__global__ __launch_bounds__(256) void ln_kernel(
    const float* __restrict__ x, const float* __restrict__ w,
    const float* __restrict__ b, unsigned short* __restrict__ yh)
{
    const int t = blockIdx.x;
    const float* xr = x + (size_t)t * DMODEL;
    unsigned short* yhr = yh + (size_t)t * DMODEL;
    const int tid = threadIdx.x;

    float v0 = xr[tid];
    float v1 = xr[tid + 256];
    float v2 = xr[tid + 512];
    float s = v0 + v1 + v2;
    float q = v0 * v0 + v1 * v1 + v2 * v2;

    #pragma unroll
    for (int off = 16; off > 0; off >>= 1) {
        s += __shfl_xor_sync(0xFFFFFFFFu, s, off);
        q += __shfl_xor_sync(0xFFFFFFFFu, q, off);
    }
    __shared__ float ss[8], sq[8];
    const int wid = tid >> 5, lid = tid & 31;
    if (lid == 0) { ss[wid] = s; sq[wid] = q; }
    __syncthreads();
    if (tid == 0) {
        float S = 0.f, Q = 0.f;
        #pragma unroll
        for (int i = 0; i < 8; i++) { S += ss[i]; Q += sq[i]; }
        float m = S * (1.0f / DMODEL);
        float var = Q * (1.0f / DMODEL) - m * m;
        ss[0] = m;
        sq[0] = rsqrtf(var + 1e-5f);
    }
    __syncthreads();
    const float m = ss[0], r = sq[0];
    float o0 = (v0 - m) * r * w[tid]       + b[tid];
    float o1 = (v1 - m) * r * w[tid + 256] + b[tid + 256];
    float o2 = (v2 - m) * r * w[tid + 512] + b[tid + 512];
    yhr[tid]       = f2h(o0);
    yhr[tid + 256] = f2h(o1);
    yhr[tid + 512] = f2h(o2);
}

// ---------------- Windowed attention (vectorized register-tiled, fp16 qkv in) -----
// Padded to 56 rows; q/k/v row stride 68 floats (rows 16B-aligned); scores 56x56.
#define AP 56
#define QSTR 68
#define ATTN_SMEM ((3 * AP * QSTR + AP * AP) * 4)   // 58240 bytes

__global__ __launch_bounds__(256) void attn_kernel(
    const unsigned short* __restrict__ qkv, unsigned short* __restrict__ oh)
{
    extern __shared__ float asmem[];
    float* sq = asmem;
    float* sk = sq + AP * QSTR;
    float* sv = sk + AP * QSTR;
    float* sp = sv + AP * QSTR;

    const int w  = blockIdx.x / NHEAD;
    const int hd = blockIdx.x % NHEAD;
    const int t0 = w * WS2;
    const int tid = threadIdx.x;

    // load q/k/v as uint4 (8 halves) and convert to fp32 smem (56 rows x 8 chunks)
    for (int i = tid; i < AP * 8; i += 256) {
        int r = i >> 3;
        int c8 = (i & 7) * 8;
        float qf[8], kf[8], vf[8];
        if (r < WS2) {
            size_t base = (size_t)(t0 + r) * D3 + hd * DHEAD + c8;
            uint4 qu = *(const uint4*)(qkv + base);
            uint4 ku = *(const uint4*)(qkv + base + DMODEL);
            uint4 vu = *(const uint4*)(qkv + base + 2 * DMODEL);
            const unsigned* qp = (const unsigned*)&qu;
            const unsigned* kp = (const unsigned*)&ku;
            const unsigned* vp = (const unsigned*)&vu;
            #pragma unroll
            for (int e = 0; e < 4; e++) {
                qf[2 * e]     = h2f((unsigned short)(qp[e] & 0xFFFFu));
                qf[2 * e + 1] = h2f((unsigned short)(qp[e] >> 16));
                kf[2 * e]     = h2f((unsigned short)(kp[e] & 0xFFFFu));
                kf[2 * e + 1] = h2f((unsigned short)(kp[e] >> 16));
                vf[2 * e]     = h2f((unsigned short)(vp[e] & 0xFFFFu));
                vf[2 * e + 1] = h2f((unsigned short)(vp[e] >> 16));
            }
        } else {
            #pragma unroll
            for (int e = 0; e < 8; e++) { qf[e] = 0.f; kf[e] = 0.f; vf[e] = 0.f; }
        }
        float4 a, bq;
        a.x = qf[0]; a.y = qf[1]; a.z = qf[2]; a.w = qf[3];
        bq.x = qf[4]; bq.y = qf[5]; bq.z = qf[6]; bq.w = qf[7];
        *(float4*)(sq + r * QSTR + c8)     = a;
        *(float4*)(sq + r * QSTR + c8 + 4) = bq;
        a.x = kf[0]; a.y = kf[1]; a.z = kf[2]; a.w = kf[3];
        bq.x = kf[4]; bq.y = kf[5]; bq.z = kf[6]; bq.w = kf[7];
        *(float4*)(sk + r * QSTR + c8)     = a;
        *(float4*)(sk + r * QSTR + c8 + 4) = bq;
        a.x = vf[0]; a.y = vf[1]; a.z = vf[2]; a.w = vf[3];
        bq.x = vf[4]; bq.y = vf[5]; bq.z = vf[6]; bq.w = vf[7];
        *(float4*)(sv + r * QSTR + c8)     = a;
        *(float4*)(sv + r * QSTR + c8 + 4) = bq;
    }
    __syncthreads();

    // phase 1: scores (4x4 per thread, float4 over d)
    {
        const int tj = tid % 14;
        const int ti = tid / 14;
        if (ti < 14) {
            float acc[4][4];
            #pragma unroll
            for (int i = 0; i < 4; i++)
                #pragma unroll
                for (int j = 0; j < 4; j++) acc[i][j] = 0.f;
            #pragma unroll 4
            for (int d = 0; d < DHEAD; d += 4) {
                float4 ra[4], rb[4];
                #pragma unroll
                for (int i = 0; i < 4; i++)
                    ra[i] = *(const float4*)(sq + (ti * 4 + i) * QSTR + d);
                #pragma unroll
                for (int j = 0; j < 4; j++)
                    rb[j] = *(const float4*)(sk + (tj * 4 + j) * QSTR + d);
                #pragma unroll
                for (int i = 0; i < 4; i++)
                    #pragma unroll
                    for (int j = 0; j < 4; j++) {
                        acc[i][j] = fmaf(ra[i].x, rb[j].x, acc[i][j]);
                        acc[i][j] = fmaf(ra[i].y, rb[j].y, acc[i][j]);
                        acc[i][j] = fmaf(ra[i].z, rb[j].z, acc[i][j]);
                        acc[i][j] = fmaf(ra[i].w, rb[j].w, acc[i][j]);
                    }
            }
            #pragma unroll
            for (int i = 0; i < 4; i++)
                #pragma unroll
                for (int j = 0; j < 4; j++)
                    sp[(ti * 4 + i) * AP + tj * 4 + j] = acc[i][j] * 0.125f;
        }
    }
    __syncthreads();

    // softmax: warp-parallel — one warp per row, lanes over columns
    {
        const int wrp = tid >> 5;
        const int ln = tid & 31;
        for (int r = wrp; r < WS2; r += 8) {
            float v1 = (ln < WS2)      ? sp[r * AP + ln]      : -1e30f;
            float v2 = (ln + 32 < WS2) ? sp[r * AP + 32 + ln] : -1e30f;
            float mx = fmaxf(v1, v2);
            #pragma unroll
            for (int off = 16; off > 0; off >>= 1)
                mx = fmaxf(mx, __shfl_xor_sync(0xFFFFFFFFu, mx, off));
            float e1 = (ln < WS2)      ? __expf(v1 - mx) : 0.f;
            float e2 = (ln + 32 < WS2) ? __expf(v2 - mx) : 0.f;
            float sum = e1 + e2;
            #pragma unroll
            for (int off = 16; off > 0; off >>= 1)
                sum += __shfl_xor_sync(0xFFFFFFFFu, sum, off);
            float inv = 1.0f / sum;
            if (ln < WS2)      sp[r * AP + ln]      = e1 * inv;
            if (ln + 32 < WS2) sp[r * AP + 32 + ln] = e2 * inv;
        }
    }
    __syncthreads();

    // phase 2: out = P @ V (4x4 per thread, float4 V loads), fp16 output
    {
        const int tj = tid % 16;      // d block
        const int ti = tid / 16;      // row block
        if (ti < 13) {
            float acc[4][4];
            #pragma unroll
            for (int i = 0; i < 4; i++)
                #pragma unroll
                for (int j = 0; j < 4; j++) acc[i][j] = 0.f;
            #pragma unroll 7
            for (int kj = 0; kj < WS2; kj++) {
                float4 rb = *(const float4*)(sv + kj * QSTR + tj * 4);
                float ra[4];
                #pragma unroll
                for (int i = 0; i < 4; i++) ra[i] = sp[(ti * 4 + i) * AP + kj];
                #pragma unroll
                for (int i = 0; i < 4; i++) {
                    acc[i][0] = fmaf(ra[i], rb.x, acc[i][0]);
                    acc[i][1] = fmaf(ra[i], rb.y, acc[i][1]);
                    acc[i][2] = fmaf(ra[i], rb.z, acc[i][2]);
                    acc[i][3] = fmaf(ra[i], rb.w, acc[i][3]);
                }
            }
            #pragma unroll
            for (int i = 0; i < 4; i++) {
                const int qi = ti * 4 + i;
                if (qi < WS2) {
                    size_t obase = (size_t)(t0 + qi) * DMODEL + hd * DHEAD + tj * 4;
                    unsigned p0 = (unsigned)f2h(acc[i][0]) | ((unsigned)f2h(acc[i][1]) << 16);
                    unsigned p1 = (unsigned)f2h(acc[i][2]) | ((unsigned)f2h(acc[i][3]) << 16);
                    *(unsigned*)(oh + obase)     = p0;
                    *(unsigned*)(oh + obase + 2) = p1;
                }
            }
        }
    }
}

// ---------------- asm helpers ----------------
__device__ __forceinline__ unsigned smem_u32(const void* p)
{
    unsigned a;
    asm volatile("{ .reg .u64 t; cvta.to.shared.u64 t, %1; cvt.u32.u64 %0, t; }"
                 : "=r"(a) : "l"(p));
    return a;
}

__device__ __forceinline__ void ldsm4a(unsigned* r, unsigned addr)
{
    asm volatile("ldmatrix.sync.aligned.m8n8.x4.shared.b16 {%0,%1,%2,%3}, [%4];"
                 : "=r"(r[0]), "=r"(r[1]), "=r"(r[2]), "=r"(r[3]) : "r"(addr));
}

__device__ __forceinline__ void mma_f16(float* c, const unsigned* a, unsigned b0, unsigned b1)
{
    asm volatile("mma.sync.aligned.m16n8k16.row.col.f32.f16.f16.f32 "
                 "{%0,%1,%2,%3}, {%4,%5,%6,%7}, {%8,%9}, {%0,%1,%2,%3};"
                 : "+f"(c[0]), "+f"(c[1]), "+f"(c[2]), "+f"(c[3])
                 : "r"(a[0]), "r"(a[1]), "r"(a[2]), "r"(a[3]), "r"(b0), "r"(b1));
}

__device__ __forceinline__ void cp16(unsigned dst, const void* src)
{
    asm volatile("cp.async.cg.shared.global [%0], [%1], 16;"
                 :: "r"(dst), "l"(src) : "memory");
}

__device__ __forceinline__ void cp_commit()
{
    asm volatile("cp.async.commit_group;" ::: "memory");
}

__device__ __forceinline__ void cp_wait2()
{
    asm volatile("cp.async.wait_group 2;" ::: "memory");
}

__device__ __forceinline__ void cp_wait0()
{
    asm volatile("cp.async.wait_group 0;" ::: "memory");
}

// ---------------- fp16 tensor-core GEMM (cp.async 3-stage pipeline) ---------------
// C = act(A @ B^T + bias) (+ res); fp16 A [M,K], B [N,K]; block 128x128, K-chunk 32.
// 8 warps, warp tile 64x32, mma.m16n8k16.f16; smem rows 80B (64B data + 16B pad).
#define ROWB 80
#define PLANEB (128 * ROWB)          // 10240
#define STAGEB (2 * PLANEB)          // 20480 (A plane + B plane)
#define NSTAGE 3
#define SMEMB  (NSTAGE * STAGEB)     // 61440

template <bool GELU, bool RES, bool HALFOUT>
__global__ __launch_bounds__(256) void gemm_f16(
    const unsigned short* __restrict__ Ah,
    const unsigned short* __restrict__ Bh,
    const float* __restrict__ bias,
    const float* __restrict__ res,
    float* __restrict__ C,
    unsigned short* __restrict__ Ch,
    int N, int K)
{
    extern __shared__ unsigned char dsm[];
    const unsigned sbase = smem_u32(dsm);
    const int tid = threadIdx.x;
    const int lane = tid & 31;
    const int wid = tid >> 5;
    const int wm = wid & 1;
    const int wn = wid >> 1;
    const int bm = blockIdx.y * 128;
    const int bn = blockIdx.x * 128;

    float acc[4][4][4];
    #pragma unroll
    for (int i = 0; i < 4; i++)
        #pragma unroll
        for (int j = 0; j < 4; j++)
            #pragma unroll
            for (int k = 0; k < 4; k++) acc[i][j][k] = 0.f;

    // loader: rows r0 and r0+64, 16B chunk ch (8 halves) of the 64B k-chunk row
    const int r0 = tid >> 2;
    const int ch = tid & 3;
    const unsigned short* gA = Ah + (size_t)(bm + r0) * K + ch * 8;
    const unsigned short* gB = Bh + (size_t)(bn + r0) * K + ch * 8;
    const size_t rstep = (size_t)64 * K;
    const unsigned drow0 = r0 * ROWB + ch * 16;
    const unsigned drow1 = (r0 + 64) * ROWB + ch * 16;
    const int nkc = K / 32;

    // prologue: issue stages 0 and 1
    {
        const unsigned st = sbase;
        cp16(st + drow0,          gA);
        cp16(st + drow1,          gA + rstep);
        cp16(st + PLANEB + drow0, gB);
        cp16(st + PLANEB + drow1, gB + rstep);
        cp_commit();
        const unsigned st1 = sbase + STAGEB;
        cp16(st1 + drow0,          gA + 32);
        cp16(st1 + drow1,          gA + 32 + rstep);
        cp16(st1 + PLANEB + drow0, gB + 32);
        cp16(st1 + PLANEB + drow1, gB + 32 + rstep);
        cp_commit();
    }

    int stage = 0;
    for (int kc = 0; kc < nkc; kc++) {
        if (kc + 2 < nkc) {
            const int snext = (stage + 2 >= NSTAGE) ? (stage + 2 - NSTAGE) : (stage + 2);
            const unsigned st = sbase + snext * STAGEB;
            const int ko = (kc + 2) * 32;
            cp16(st + drow0,          gA + ko);
            cp16(st + drow1,          gA + ko + rstep);
            cp16(st + PLANEB + drow0, gB + ko);
            cp16(st + PLANEB + drow1, gB + ko + rstep);
            cp_commit();
            cp_wait2();
        } else {
            cp_wait0();
        }
        __syncthreads();

        const unsigned st = sbase + stage * STAGEB;
        #pragma unroll
        for (int ks = 0; ks < 2; ks++) {
            const unsigned abase = st + (wm * 64 + (lane & 15)) * ROWB
                                   + ks * 32 + ((lane >> 4) << 4);
            const unsigned bbase = st + PLANEB + (wn * 32 + (lane & 15)) * ROWB
                                   + ks * 32 + ((lane >> 4) << 4);
            unsigned ah[4][4];
            #pragma unroll
            for (int mi = 0; mi < 4; mi++)
                ldsm4a(ah[mi], abase + mi * 16 * ROWB);
            unsigned bh[2][4];
            #pragma unroll
            for (int nj = 0; nj < 2; nj++)
                ldsm4a(bh[nj], bbase + nj * 16 * ROWB);
            #pragma unroll
            for (int mi = 0; mi < 4; mi++)
                #pragma unroll
                for (int ni = 0; ni < 4; ni++)
                    mma_f16(acc[mi][ni], ah[mi], bh[ni >> 1][ni & 1],
                            bh[ni >> 1][(ni & 1) + 2]);
        }
        __syncthreads();
        stage = (stage + 1 >= NSTAGE) ? 0 : (stage + 1);
    }

    // epilogue
    #pragma unroll
    for (int mi = 0; mi < 4; mi++) {
        #pragma unroll
        for (int ni = 0; ni < 4; ni++) {
            const int col = bn + wn * 32 + ni * 8 + (lane & 3) * 2;
            const float bs0 = bias[col];
            const float bs1 = bias[col + 1];
            #pragma unroll
            for (int half = 0; half < 2; half++) {
                const int row = bm + wm * 64 + mi * 16 + (lane >> 2) + half * 8;
                float v0 = acc[mi][ni][half * 2 + 0] + bs0;
                float v1 = acc[mi][ni][half * 2 + 1] + bs1;
                if (GELU) {
                    v0 = 0.5f * v0 * (1.0f + erff(v0 * 0.70710678118654752f));
                    v1 = 0.5f * v1 * (1.0f + erff(v1 * 0.70710678118654752f));
                }
                if (RES) {
                    float2 r2 = *(const float2*)(res + (size_t)row * N + col);
                    v0 += r2.x;
                    v1 += r2.y;
                }
                if (HALFOUT) {
                    unsigned p = (unsigned)f2h(v0) | ((unsigned)f2h(v1) << 16);
                    *(unsigned*)(Ch + (size_t)row * N + col) = p;
                } else {
                    float2 o2;
                    o2.x = v0;
                    o2.y = v1;
                    *(float2*)(C + (size_t)row * N + col) = o2;
                }
            }
        }
    }
}

// ---------------- host-side launch ----------------
extern "C" void kernel_launch(void* const* d_in, const int* in_sizes, int n_in,
                              void* d_out, int out_size)
{
    const float* x     = (const float*)d_in[0];
    const float* Wqkv  = (const float*)d_in[1];
    const float* bqkv  = (const float*)d_in[2];
    const float* Wo    = (const float*)d_in[3];
    const float* bo    = (const float*)d_in[4];
    const float* ln1_w = (const float*)d_in[5];
    const float* ln1_b = (const float*)d_in[6];
    const float* W1    = (const float*)d_in[7];
    const float* b1    = (const float*)d_in[8];
    const float* W2    = (const float*)d_in[9];
    const float* b2    = (const float*)d_in[10];
    const float* ln2_w = (const float*)d_in[11];
    const float* ln2_b = (const float*)d_in[12];
    float* out = (float*)d_out;

    static float *p_h = nullptr;
    static unsigned short *p_qkvh = nullptr, *p_yh = nullptr, *p_oh = nullptr;
    static unsigned short *p_fh = nullptr, *p_wh = nullptr;
    if (!p_h) {
        cudaGetSymbolAddress((void**)&p_h,    g_h);
        cudaGetSymbolAddress((void**)&p_qkvh, g_qkvh);
        cudaGetSymbolAddress((void**)&p_yh,   g_yh);
        cudaGetSymbolAddress((void**)&p_oh,   g_oh);
        cudaGetSymbolAddress((void**)&p_fh,   g_fh);
        cudaGetSymbolAddress((void**)&p_wh,   g_wh);
        cudaFuncSetAttribute(gemm_f16<false, false, true>,
                             cudaFuncAttributeMaxDynamicSharedMemorySize, SMEMB);
        cudaFuncSetAttribute(gemm_f16<false, true, false>,
                             cudaFuncAttributeMaxDynamicSharedMemorySize, SMEMB);
        cudaFuncSetAttribute(gemm_f16<true, false, true>,
                             cudaFuncAttributeMaxDynamicSharedMemorySize, SMEMB);
        cudaFuncSetAttribute(attn_kernel,
                             cudaFuncAttributeMaxDynamicSharedMemorySize, ATTN_SMEM);
    }

    const dim3 blk(256);
    const dim3 grid_qkv(D3 / 128,     T_TOKENS / 128);
    const dim3 grid_d  (DMODEL / 128, T_TOKENS / 128);
    const dim3 grid_ff (FFDIM / 128,  T_TOKENS / 128);

    for (int l = 0; l < 2; l++) {
        const float* hin  = (l == 0) ? x : p_h;
        float* hout2 = (l == 1) ? out : p_h;   // last FFN GEMM writes final output

        // pre-norm attention
        ln_kernel<<<T_TOKENS, blk>>>(hin, ln1_w + l * DMODEL, ln1_b + l * DMODEL, p_yh);
        cvt_kernel<<<(D3 * DMODEL) / 1024, blk>>>(Wqkv + (size_t)l * D3 * DMODEL, p_wh);
        gemm_f16<false, false, true><<<grid_qkv, blk, SMEMB>>>(
            p_yh, p_wh, bqkv + (size_t)l * D3,
            nullptr, nullptr, p_qkvh, D3, DMODEL);
        attn_kernel<<<NWIN * NHEAD, blk, ATTN_SMEM>>>(p_qkvh, p_oh);
        cvt_kernel<<<(DMODEL * DMODEL) / 1024, blk>>>(Wo + (size_t)l * DMODEL * DMODEL, p_wh);
        gemm_f16<false, true, false><<<grid_d, blk, SMEMB>>>(
            p_oh, p_wh, bo + (size_t)l * DMODEL,
            hin, p_h, nullptr, DMODEL, DMODEL);

        // pre-norm FFN
        ln_kernel<<<T_TOKENS, blk>>>(p_h, ln2_w + l * DMODEL, ln2_b + l * DMODEL, p_yh);
        cvt_kernel<<<(FFDIM * DMODEL) / 1024, blk>>>(W1 + (size_t)l * FFDIM * DMODEL, p_wh);
        gemm_f16<true, false, true><<<grid_ff, blk, SMEMB>>>(
            p_yh, p_wh, b1 + (size_t)l * FFDIM,
            nullptr, nullptr, p_fh, FFDIM, DMODEL);
        cvt_kernel<<<(DMODEL * FFDIM) / 1024, blk>>>(W2 + (size_t)l * DMODEL * FFDIM, p_wh);
        gemm_f16<false, true, false><<<grid_d, blk, SMEMB>>>(
            p_fh, p_wh, b2 + (size_t)l * DMODEL,
            p_h, hout2, nullptr, DMODEL, FFDIM);
    }
    (void)in_sizes; (void)n_in; (void)out_size;
}

// round 14
// speedup vs baseline: 7.0795x; 1.1003x over previous
#include <cuda_runtime.h>
#include <math.h>

// Problem constants
#define T_TOKENS 25088      // 8 * 3136
#define DMODEL   768
#define NHEAD    12
#define DHEAD    64
#define FFDIM    3072
#define WS2      49
#define NWIN     512        // T_TOKENS / 49
#define D3       2304       // 3 * DMODEL

// ---------------- scratch (device globals; no allocation allowed) ----------------
__device__ __align__(128) float g_h[(size_t)T_TOKENS * DMODEL];
// fp16 planes
__device__ __align__(128) unsigned short g_qkvh[(size_t)T_TOKENS * D3];
__device__ __align__(128) unsigned short g_yh[(size_t)T_TOKENS * DMODEL];
__device__ __align__(128) unsigned short g_oh[(size_t)T_TOKENS * DMODEL];
__device__ __align__(128) unsigned short g_fh[(size_t)T_TOKENS * FFDIM];
__device__ __align__(128) unsigned short g_wh[(size_t)FFDIM * DMODEL];

// ---------------- fp16 helpers (inline PTX; no cuda_fp16.h) ----------------
__device__ __forceinline__ unsigned short f2h(float f)
{
    unsigned short h;
    asm("cvt.rn.f16.f32 %0, %1;" : "=h"(h) : "f"(f));
    return h;
}

// ---------------- weight convert: fp32 -> fp16 plane ----------------
__global__ __launch_bounds__(256) void cvt_kernel(
    const float* __restrict__ src, unsigned short* __restrict__ dst)
{
    const int i = (blockIdx.x * 256 + threadIdx.x) * 4;
    float4 v = *(const float4*)(src + i);
    unsigned p0 = (unsigned)f2h(v.x) | ((unsigned)f2h(v.y) << 16);
    unsigned p1 = (unsigned)f2h(v.z) | ((unsigned)f2h(v.w) << 16);
    uint2 o;
    o.x = p0;
    o.y = p1;
    *(uint2*)(dst + i) = o;
}

// ---------------- LayerNorm: one block per token; writes fp16 plane ---------------
__global__ __launch_bounds__(256) void ln_kernel(
    const float* __restrict__ x, const float* __restrict__ w,
    const float* __restrict__ b, unsigned short* __restrict__ yh)
{
    const int t = blockIdx.x;
    const float* xr = x + (size_t)t * DMODEL;
    unsigned short* yhr = yh + (size_t)t * DMODEL;
    const int tid = threadIdx.x;

    float v0 = xr[tid];
    float v1 = xr[tid + 256];
    float v2 = xr[tid + 512];
    float s = v0 + v1 + v2;
    float q = v0 * v0 + v1 * v1 + v2 * v2;

    #pragma unroll
    for (int off = 16; off > 0; off >>= 1) {
        s += __shfl_xor_sync(0xFFFFFFFFu, s, off);
        q += __shfl_xor_sync(0xFFFFFFFFu, q, off);
    }
    __shared__ float ss[8], sq[8];
    const int wid = tid >> 5, lid = tid & 31;
    if (lid == 0) { ss[wid] = s; sq[wid] = q; }
    __syncthreads();
    if (tid == 0) {
        float S = 0.f, Q = 0.f;
        #pragma unroll
        for (int i = 0; i < 8; i++) { S += ss[i]; Q += sq[i]; }
        float m = S * (1.0f / DMODEL);
        float var = Q * (1.0f / DMODEL) - m * m;
        ss[0] = m;
        sq[0] = rsqrtf(var + 1e-5f);
    }
    __syncthreads();
    const float m = ss[0], r = sq[0];
    float o0 = (v0 - m) * r * w[tid]       + b[tid];
    float o1 = (v1 - m) * r * w[tid + 256] + b[tid + 256];
    float o2 = (v2 - m) * r * w[tid + 512] + b[tid + 512];
    yhr[tid]       = f2h(o0);
    yhr[tid + 256] = f2h(o1);
    yhr[tid + 512] = f2h(o2);
}

// ---------------- asm helpers ----------------
__device__ __forceinline__ unsigned smem_u32(const void* p)
{
    unsigned a;
    asm volatile("{ .reg .u64 t; cvta.to.shared.u64 t, %1; cvt.u32.u64 %0, t; }"
                 : "=r"(a) : "l"(p));
    return a;
}

__device__ __forceinline__ void ldsm4a(unsigned* r, unsigned addr)
{
    asm volatile("ldmatrix.sync.aligned.m8n8.x4.shared.b16 {%0,%1,%2,%3}, [%4];"
                 : "=r"(r[0]), "=r"(r[1]), "=r"(r[2]), "=r"(r[3]) : "r"(addr));
}

__device__ __forceinline__ void mma_f16(float* c, const unsigned* a, unsigned b0, unsigned b1)
{
    asm volatile("mma.sync.aligned.m16n8k16.row.col.f32.f16.f16.f32 "
                 "{%0,%1,%2,%3}, {%4,%5,%6,%7}, {%8,%9}, {%0,%1,%2,%3};"
                 : "+f"(c[0]), "+f"(c[1]), "+f"(c[2]), "+f"(c[3])
                 : "r"(a[0]), "r"(a[1]), "r"(a[2]), "r"(a[3]), "r"(b0), "r"(b1));
}

__device__ __forceinline__ void cp16(unsigned dst, const void* src)
{
    asm volatile("cp.async.cg.shared.global [%0], [%1], 16;"
                 :: "r"(dst), "l"(src) : "memory");
}

__device__ __forceinline__ void cp_commit()
{
    asm volatile("cp.async.commit_group;" ::: "memory");
}

__device__ __forceinline__ void cp_wait2()
{
    asm volatile("cp.async.wait_group 2;" ::: "memory");
}

__device__ __forceinline__ void cp_wait0()
{
    asm volatile("cp.async.wait_group 0;" ::: "memory");
}

// ---------------- Windowed attention (tensor-core, fp16 end-to-end) ----------------
// One block per (window, head), 128 threads = 4 warps. Tiles padded to 64.
// smem: Q, K, Vt, P fp16 64x72-half rows (144B); S fp32 56x60.
#define HROWB 144
#define QOFF  0
#define KOFF  9216
#define VTOFF 18432
#define POFF  27648
#define SOFF  36864
#define SSTR  60
#define ATTN_SMEM (36864 + 56 * SSTR * 4)   // 50304 bytes

__global__ __launch_bounds__(128) void attn_kernel(
    const unsigned short* __restrict__ qkv, unsigned short* __restrict__ oh)
{
    extern __shared__ unsigned char hsm[];
    const unsigned sbase = smem_u32(hsm);
    const int w  = blockIdx.x / NHEAD;
    const int hd = blockIdx.x % NHEAD;
    const int t0 = w * WS2;
    const int tid = threadIdx.x;
    const int lane = tid & 31;
    const int wi = tid >> 5;

    // zero the fp16 regions (Q,K,Vt,P = 36864 bytes = 2304 uint4)
    {
        uint4 z;
        z.x = 0; z.y = 0; z.z = 0; z.w = 0;
        for (int i = tid; i < 2304; i += 128)
            ((uint4*)hsm)[i] = z;
    }
    __syncthreads();

    // load q,k rows; v transposed (49 rows x 8 chunks of 8 halves)
    for (int i = tid; i < WS2 * 8; i += 128) {
        int r = i >> 3;
        int c8 = (i & 7) * 8;
        size_t base = (size_t)(t0 + r) * D3 + hd * DHEAD + c8;
        uint4 qu = *(const uint4*)(qkv + base);
        uint4 ku = *(const uint4*)(qkv + base + DMODEL);
        uint4 vu = *(const uint4*)(qkv + base + 2 * DMODEL);
        *(uint4*)(hsm + QOFF + r * HROWB + c8 * 2) = qu;
        *(uint4*)(hsm + KOFF + r * HROWB + c8 * 2) = ku;
        const unsigned short* vp = (const unsigned short*)&vu;
        #pragma unroll
        for (int e = 0; e < 8; e++)
            *(unsigned short*)(hsm + VTOFF + (c8 + e) * HROWB + r * 2) = vp[e];
    }
    __syncthreads();

    float* sS = (float*)(hsm + SOFF);

    // phase 1: S = Q @ K^T (warp wi: rows 16*wi..16*wi+15, all 64 cols)
    {
        float acc[8][4];
        #pragma unroll
        for (int i = 0; i < 8; i++)
            #pragma unroll
            for (int j = 0; j < 4; j++) acc[i][j] = 0.f;
        #pragma unroll
        for (int ks = 0; ks < 4; ks++) {
            unsigned aq[4];
            ldsm4a(aq, sbase + QOFF + (wi * 16 + (lane & 15)) * HROWB
                       + ks * 32 + ((lane >> 4) << 4));
            unsigned bk[4][4];
            #pragma unroll
            for (int nb = 0; nb < 4; nb++)
                ldsm4a(bk[nb], sbase + KOFF + (nb * 16 + (lane & 15)) * HROWB
                               + ks * 32 + ((lane >> 4) << 4));
            #pragma unroll
            for (int nt = 0; nt < 8; nt++)
                mma_f16(acc[nt], aq, bk[nt >> 1][nt & 1], bk[nt >> 1][(nt & 1) + 2]);
        }
        #pragma unroll
        for (int nt = 0; nt < 8; nt++) {
            #pragma unroll
            for (int half = 0; half < 2; half++) {
                int row = wi * 16 + (lane >> 2) + half * 8;
                int col = nt * 8 + (lane & 3) * 2;
                if (row < 56 && col < 56) {
                    sS[row * SSTR + col]     = acc[nt][half * 2 + 0] * 0.125f;
                    sS[row * SSTR + col + 1] = acc[nt][half * 2 + 1] * 0.125f;
                }
            }
        }
    }
    __syncthreads();

    // softmax (4 warps, one row per warp iteration), write fp16 P
    {
        unsigned short* sP = (unsigned short*)(hsm + POFF);
        for (int r = wi; r < WS2; r += 4) {
            float v1 = (lane < WS2)      ? sS[r * SSTR + lane]      : -1e30f;
            float v2 = (lane + 32 < WS2) ? sS[r * SSTR + 32 + lane] : -1e30f;
            float mx = fmaxf(v1, v2);
            #pragma unroll
            for (int off = 16; off > 0; off >>= 1)
                mx = fmaxf(mx, __shfl_xor_sync(0xFFFFFFFFu, mx, off));
            float e1 = (lane < WS2)      ? __expf(v1 - mx) : 0.f;
            float e2 = (lane + 32 < WS2) ? __expf(v2 - mx) : 0.f;
            float sum = e1 + e2;
            #pragma unroll
            for (int off = 16; off > 0; off >>= 1)
                sum += __shfl_xor_sync(0xFFFFFFFFu, sum, off);
            float inv = 1.0f / sum;
            if (lane < WS2)      sP[r * 72 + lane]      = f2h(e1 * inv);
            if (lane + 32 < WS2) sP[r * 72 + 32 + lane] = f2h(e2 * inv);
        }
    }
    __syncthreads();

    // phase 2: O = P @ Vt^T (A = P [rows, j], B = Vt [d, j]; j padded with zeros)
    {
        float acc[8][4];
        #pragma unroll
        for (int i = 0; i < 8; i++)
            #pragma unroll
            for (int j = 0; j < 4; j++) acc[i][j] = 0.f;
        #pragma unroll
        for (int ks = 0; ks < 4; ks++) {
            unsigned ap[4];
            ldsm4a(ap, sbase + POFF + (wi * 16 + (lane & 15)) * HROWB
                       + ks * 32 + ((lane >> 4) << 4));
            unsigned bv[4][4];
            #pragma unroll
            for (int nb = 0; nb < 4; nb++)
                ldsm4a(bv[nb], sbase + VTOFF + (nb * 16 + (lane & 15)) * HROWB
                               + ks * 32 + ((lane >> 4) << 4));
            #pragma unroll
            for (int nt = 0; nt < 8; nt++)
                mma_f16(acc[nt], ap, bv[nt >> 1][nt & 1], bv[nt >> 1][(nt & 1) + 2]);
        }
        #pragma unroll
        for (int nt = 0; nt < 8; nt++) {
            #pragma unroll
            for (int half = 0; half < 2; half++) {
                int row = wi * 16 + (lane >> 2) + half * 8;
                int col = nt * 8 + (lane & 3) * 2;
                if (row < WS2) {
                    unsigned p = (unsigned)f2h(acc[nt][half * 2 + 0])
                               | ((unsigned)f2h(acc[nt][half * 2 + 1]) << 16);
                    *(unsigned*)(oh + (size_t)(t0 + row) * DMODEL + hd * DHEAD + col) = p;
                }
            }
        }
    }
}

// ---------------- fp16 tensor-core GEMM (cp.async 3-stage pipeline) ---------------
// C = act(A @ B^T + bias) (+ res); fp16 A [M,K], B [N,K]; block 128x128, K-chunk 32.
// 8 warps, warp tile 64x32, mma.m16n8k16.f16; smem rows 80B (64B data + 16B pad).
#define ROWB 80
#define PLANEB (128 * ROWB)          // 10240
#define STAGEB (2 * PLANEB)          // 20480 (A plane + B plane)
#define NSTAGE 3
#define SMEMB  (NSTAGE * STAGEB)     // 61440

template <bool GELU, bool RES, bool HALFOUT>
__global__ __launch_bounds__(256) void gemm_f16(
    const unsigned short* __restrict__ Ah,
    const unsigned short* __restrict__ Bh,
    const float* __restrict__ bias,
    const float* __restrict__ res,
    float* __restrict__ C,
    unsigned short* __restrict__ Ch,
    int N, int K)
{
    extern __shared__ unsigned char dsm[];
    const unsigned sbase = smem_u32(dsm);
    const int tid = threadIdx.x;
    const int lane = tid & 31;
    const int wid = tid >> 5;
    const int wm = wid & 1;
    const int wn = wid >> 1;
    const int bm = blockIdx.y * 128;
    const int bn = blockIdx.x * 128;

    float acc[4][4][4];
    #pragma unroll
    for (int i = 0; i < 4; i++)
        #pragma unroll
        for (int j = 0; j < 4; j++)
            #pragma unroll
            for (int k = 0; k < 4; k++) acc[i][j][k] = 0.f;

    // loader: rows r0 and r0+64, 16B chunk ch (8 halves) of the 64B k-chunk row
    const int r0 = tid >> 2;
    const int ch = tid & 3;
    const unsigned short* gA = Ah + (size_t)(bm + r0) * K + ch * 8;
    const unsigned short* gB = Bh + (size_t)(bn + r0) * K + ch * 8;
    const size_t rstep = (size_t)64 * K;
    const unsigned drow0 = r0 * ROWB + ch * 16;
    const unsigned drow1 = (r0 + 64) * ROWB + ch * 16;
    const int nkc = K / 32;

    // prologue: issue stages 0 and 1
    {
        const unsigned st = sbase;
        cp16(st + drow0,          gA);
        cp16(st + drow1,          gA + rstep);
        cp16(st + PLANEB + drow0, gB);
        cp16(st + PLANEB + drow1, gB + rstep);
        cp_commit();
        const unsigned st1 = sbase + STAGEB;
        cp16(st1 + drow0,          gA + 32);
        cp16(st1 + drow1,          gA + 32 + rstep);
        cp16(st1 + PLANEB + drow0, gB + 32);
        cp16(st1 + PLANEB + drow1, gB + 32 + rstep);
        cp_commit();
    }

    int stage = 0;
    for (int kc = 0; kc < nkc; kc++) {
        if (kc + 2 < nkc) {
            const int snext = (stage + 2 >= NSTAGE) ? (stage + 2 - NSTAGE) : (stage + 2);
            const unsigned st = sbase + snext * STAGEB;
            const int ko = (kc + 2) * 32;
            cp16(st + drow0,          gA + ko);
            cp16(st + drow1,          gA + ko + rstep);
            cp16(st + PLANEB + drow0, gB + ko);
            cp16(st + PLANEB + drow1, gB + ko + rstep);
            cp_commit();
            cp_wait2();
        } else {
            cp_wait0();
        }
        __syncthreads();

        const unsigned st = sbase + stage * STAGEB;
        #pragma unroll
        for (int ks = 0; ks < 2; ks++) {
            const unsigned abase = st + (wm * 64 + (lane & 15)) * ROWB
                                   + ks * 32 + ((lane >> 4) << 4);
            const unsigned bbase = st + PLANEB + (wn * 32 + (lane & 15)) * ROWB
                                   + ks * 32 + ((lane >> 4) << 4);
            unsigned ah[4][4];
            #pragma unroll
            for (int mi = 0; mi < 4; mi++)
                ldsm4a(ah[mi], abase + mi * 16 * ROWB);
            unsigned bh[2][4];
            #pragma unroll
            for (int nj = 0; nj < 2; nj++)
                ldsm4a(bh[nj], bbase + nj * 16 * ROWB);
            #pragma unroll
            for (int mi = 0; mi < 4; mi++)
                #pragma unroll
                for (int ni = 0; ni < 4; ni++)
                    mma_f16(acc[mi][ni], ah[mi], bh[ni >> 1][ni & 1],
                            bh[ni >> 1][(ni & 1) + 2]);
        }
        __syncthreads();
        stage = (stage + 1 >= NSTAGE) ? 0 : (stage + 1);
    }

    // epilogue
    #pragma unroll
    for (int mi = 0; mi < 4; mi++) {
        #pragma unroll
        for (int ni = 0; ni < 4; ni++) {
            const int col = bn + wn * 32 + ni * 8 + (lane & 3) * 2;
            const float bs0 = bias[col];
            const float bs1 = bias[col + 1];
            #pragma unroll
            for (int half = 0; half < 2; half++) {
                const int row = bm + wm * 64 + mi * 16 + (lane >> 2) + half * 8;
                float v0 = acc[mi][ni][half * 2 + 0] + bs0;
                float v1 = acc[mi][ni][half * 2 + 1] + bs1;
                if (GELU) {
                    v0 = 0.5f * v0 * (1.0f + erff(v0 * 0.70710678118654752f));
                    v1 = 0.5f * v1 * (1.0f + erff(v1 * 0.70710678118654752f));
                }
                if (RES) {
                    float2 r2 = *(const float2*)(res + (size_t)row * N + col);
                    v0 += r2.x;
                    v1 += r2.y;
                }
                if (HALFOUT) {
                    unsigned p = (unsigned)f2h(v0) | ((unsigned)f2h(v1) << 16);
                    *(unsigned*)(Ch + (size_t)row * N + col) = p;
                } else {
                    float2 o2;
                    o2.x = v0;
                    o2.y = v1;
                    *(float2*)(C + (size_t)row * N + col) = o2;
                }
            }
        }
    }
}

// ---------------- host-side launch ----------------
extern "C" void kernel_launch(void* const* d_in, const int* in_sizes, int n_in,
                              void* d_out, int out_size)
{
    const float* x     = (const float*)d_in[0];
    const float* Wqkv  = (const float*)d_in[1];
    const float* bqkv  = (const float*)d_in[2];
    const float* Wo    = (const float*)d_in[3];
    const float* bo    = (const float*)d_in[4];
    const float* ln1_w = (const float*)d_in[5];
    const float* ln1_b = (const float*)d_in[6];
    const float* W1    = (const float*)d_in[7];
    const float* b1    = (const float*)d_in[8];
    const float* W2    = (const float*)d_in[9];
    const float* b2    = (const float*)d_in[10];
    const float* ln2_w = (const float*)d_in[11];
    const float* ln2_b = (const float*)d_in[12];
    float* out = (float*)d_out;

    static float *p_h = nullptr;
    static unsigned short *p_qkvh = nullptr, *p_yh = nullptr, *p_oh = nullptr;
    static unsigned short *p_fh = nullptr, *p_wh = nullptr;
    if (!p_h) {
        cudaGetSymbolAddress((void**)&p_h,    g_h);
        cudaGetSymbolAddress((void**)&p_qkvh, g_qkvh);
        cudaGetSymbolAddress((void**)&p_yh,   g_yh);
        cudaGetSymbolAddress((void**)&p_oh,   g_oh);
        cudaGetSymbolAddress((void**)&p_fh,   g_fh);
        cudaGetSymbolAddress((void**)&p_wh,   g_wh);
        cudaFuncSetAttribute(gemm_f16<false, false, true>,
                             cudaFuncAttributeMaxDynamicSharedMemorySize, SMEMB);
        cudaFuncSetAttribute(gemm_f16<false, true, false>,
                             cudaFuncAttributeMaxDynamicSharedMemorySize, SMEMB);
        cudaFuncSetAttribute(gemm_f16<true, false, true>,
                             cudaFuncAttributeMaxDynamicSharedMemorySize, SMEMB);
        cudaFuncSetAttribute(attn_kernel,
                             cudaFuncAttributeMaxDynamicSharedMemorySize, ATTN_SMEM);
    }

    const dim3 blk(256);
    const dim3 ablk(128);
    const dim3 grid_qkv(D3 / 128,     T_TOKENS / 128);
    const dim3 grid_d  (DMODEL / 128, T_TOKENS / 128);
    const dim3 grid_ff (FFDIM / 128,  T_TOKENS / 128);

    for (int l = 0; l < 2; l++) {
        const float* hin  = (l == 0) ? x : p_h;
        float* hout2 = (l == 1) ? out : p_h;   // last FFN GEMM writes final output

        // pre-norm attention
        ln_kernel<<<T_TOKENS, blk>>>(hin, ln1_w + l * DMODEL, ln1_b + l * DMODEL, p_yh);
        cvt_kernel<<<(D3 * DMODEL) / 1024, blk>>>(Wqkv + (size_t)l * D3 * DMODEL, p_wh);
        gemm_f16<false, false, true><<<grid_qkv, blk, SMEMB>>>(
            p_yh, p_wh, bqkv + (size_t)l * D3,
            nullptr, nullptr, p_qkvh, D3, DMODEL);
        attn_kernel<<<NWIN * NHEAD, ablk, ATTN_SMEM>>>(p_qkvh, p_oh);
        cvt_kernel<<<(DMODEL * DMODEL) / 1024, blk>>>(Wo + (size_t)l * DMODEL * DMODEL, p_wh);
        gemm_f16<false, true, false><<<grid_d, blk, SMEMB>>>(
            p_oh, p_wh, bo + (size_t)l * DMODEL,
            hin, p_h, nullptr, DMODEL, DMODEL);

        // pre-norm FFN
        ln_kernel<<<T_TOKENS, blk>>>(p_h, ln2_w + l * DMODEL, ln2_b + l * DMODEL, p_yh);
        cvt_kernel<<<(FFDIM * DMODEL) / 1024, blk>>>(W1 + (size_t)l * FFDIM * DMODEL, p_wh);
        gemm_f16<true, false, true><<<grid_ff, blk, SMEMB>>>(
            p_yh, p_wh, b1 + (size_t)l * FFDIM,
            nullptr, nullptr, p_fh, FFDIM, DMODEL);
        cvt_kernel<<<(DMODEL * FFDIM) / 1024, blk>>>(W2 + (size_t)l * DMODEL * FFDIM, p_wh);
        gemm_f16<false, true, false><<<grid_d, blk, SMEMB>>>(
            p_fh, p_wh, b2 + (size_t)l * DMODEL,
            p_h, hout2, nullptr, DMODEL, FFDIM);
    }
    (void)in_sizes; (void)n_in; (void)out_size;
}